// round 12
// baseline (speedup 1.0000x reference)
#include <cuda_runtime.h>
#include <cuda_bf16.h>
#include <math.h>
#include <stdint.h>

#define NL 4
#define NB 4
#define NS 1024
#define ND 768
#define NF 3072
#define NE 4
#define NV 256
#define NH 12
#define NDH 64
#define NT (NB*NS)
#define NQKV 2304

// ================= packed f32x2 helpers =================
#define FMA2(d,a,b,c) asm("fma.rn.f32x2 %0, %1, %2, %3;" : "=l"(d) : "l"(a), "l"(b), "l"(c))
#define MUL2(d,a,b)   asm("mul.rn.f32x2 %0, %1, %2;" : "=l"(d) : "l"(a), "l"(b))
#define DUP2(d,s)     asm("mov.b64 %0, {%1, %1};" : "=l"(d) : "f"(s))
#define UNP2(lo,hi,v) asm("mov.b64 {%0, %1}, %2;" : "=f"(lo), "=f"(hi) : "l"(v))

__device__ __forceinline__ uint32_t smem_u32(const void* p){
    uint32_t a;
    asm("{ .reg .u64 t; cvta.to.shared.u64 t, %1; cvt.u32.u64 %0, t; }" : "=r"(a) : "l"(p));
    return a;
}

// ldmatrix / mma wrappers (sm_80+, OK on compute_103)
#define LDSM_X4(r0,r1,r2,r3,addr) \
    asm volatile("ldmatrix.sync.aligned.m8n8.x4.shared.b16 {%0,%1,%2,%3}, [%4];" \
        : "=r"(r0),"=r"(r1),"=r"(r2),"=r"(r3) : "r"(addr))
#define LDSM_X2(r0,r1,addr) \
    asm volatile("ldmatrix.sync.aligned.m8n8.x2.shared.b16 {%0,%1}, [%2];" \
        : "=r"(r0),"=r"(r1) : "r"(addr))
#define MMA16816(d,a,b) \
    asm volatile("mma.sync.aligned.m16n8k16.row.col.f32.bf16.bf16.f32 " \
        "{%0,%1,%2,%3}, {%4,%5,%6,%7}, {%8,%9}, {%0,%1,%2,%3};" \
        : "+f"((d)[0]),"+f"((d)[1]),"+f"((d)[2]),"+f"((d)[3]) \
        : "r"((a)[0]),"r"((a)[1]),"r"((a)[2]),"r"((a)[3]), "r"((b)[0]),"r"((b)[1]))

// ================= scratch =================
__device__ float g_x[NT*ND];
__device__ float g_h[NT*ND];
__device__ float g_qkv[(size_t)NT*NQKV];
__device__ float g_h2[(size_t)NE*NT*ND];      // compact per-expert MoE outputs
__device__ float g_bqkv[NL*NQKV];
__device__ float g_sgate[NT*2];               // top-2 gates per token
__device__ int   g_slot[NT*2];                // e*NT+pos per token
__device__ int   g_eidx[NE*NT];
__device__ int   g_ecnt[NE];

__device__ __nv_bfloat16 g_hb_h[NT*ND],  g_hb_l[NT*ND];
__device__ __nv_bfloat16 g_ob_h[NT*ND],  g_ob_l[NT*ND];
__device__ __nv_bfloat16 g_xcb_h[NT*3*ND], g_xcb_l[NT*3*ND];
__device__ __nv_bfloat16 g_h1b_h[(size_t)NE*NT*NF], g_h1b_l[(size_t)NE*NT*NF];
__device__ __nv_bfloat16 g_wcT_h[ND*3*ND], g_wcT_l[ND*3*ND];
__device__ __nv_bfloat16 g_wqkvT_h[NL*NQKV*ND], g_wqkvT_l[NL*NQKV*ND];
__device__ __nv_bfloat16 g_woT_h[NL*ND*ND], g_woT_l[NL*ND*ND];
__device__ __nv_bfloat16 g_w1T_h[NL*NE*NF*ND], g_w1T_l[NL*NE*NF*ND];
__device__ __nv_bfloat16 g_w2T_h[NL*NE*ND*NF], g_w2T_l[NL*NE*ND*NF];
__device__ __nv_bfloat16 g_woutT_h[NV*ND], g_woutT_l[NV*ND];

__device__ __forceinline__ float gelu_f(float x){
    const float c = 0.7978845608028654f;
    return 0.5f*x*(1.0f + tanhf(c*(x + 0.044715f*x*x*x)));
}
__device__ __forceinline__ void split_bf(float v, __nv_bfloat16& h, __nv_bfloat16& l){
    h = __float2bfloat16(v);
    l = __float2bfloat16(v - __bfloat162float(h));
}

// ================= small kernels =================
__global__ void embed_kernel(const int* __restrict__ text, const float* __restrict__ emb){
    int t = blockIdx.x;
    int tok = text[t];
    const float* src = emb + (size_t)tok*ND;
    float* dst = g_x + (size_t)t*ND;
    for (int d = threadIdx.x; d < ND; d += blockDim.x) dst[d] = src[d];
}

__global__ void convw_kernel(const float* __restrict__ w){
    int idx = blockIdx.x*blockDim.x + threadIdx.x;
    if (idx >= ND*3*ND) return;
    int o = idx / (3*ND);
    int r = idx % (3*ND);
    int k = r / ND, i = r % ND;
    float v = w[((size_t)o*ND + i)*3 + k];
    split_bf(v, g_wcT_h[idx], g_wcT_l[idx]);
}

__global__ void wtrans_kernel(const float* __restrict__ in, __nv_bfloat16* __restrict__ hi,
                              __nv_bfloat16* __restrict__ lo, int K, int N, long long ozs){
    __shared__ float t[32][33];
    size_t zi = (size_t)blockIdx.z*K*N;
    size_t zo = (size_t)blockIdx.z*ozs;
    int n0 = blockIdx.x*32, k0 = blockIdx.y*32;
    int tx = threadIdx.x, ty = threadIdx.y;
    #pragma unroll
    for (int j=0;j<32;j+=8)
        t[ty+j][tx] = in[zi + (size_t)(k0+ty+j)*N + (n0+tx)];
    __syncthreads();
    #pragma unroll
    for (int j=0;j<32;j+=8){
        float v = t[tx][ty+j];
        size_t oi = zo + (size_t)(n0+ty+j)*K + (k0+tx);
        __nv_bfloat16 h,l; split_bf(v,h,l);
        hi[oi]=h; lo[oi]=l;
    }
}

__global__ void bpack_kernel(const float* __restrict__ bq, const float* __restrict__ bk,
                             const float* __restrict__ bv){
    int idx = blockIdx.x*blockDim.x + threadIdx.x;
    if (idx >= NL*NQKV) return;
    int layer = idx / NQKV, c = idx % NQKV;
    float v;
    if (c < ND)            v = bq[layer*ND + c];
    else if (c < 2*ND)     v = bk[layer*ND + c - ND];
    else                   v = bv[layer*ND + c - 2*ND];
    g_bqkv[idx] = v;
}

__global__ void xcat_kernel(){
    int t = blockIdx.x;
    int s = t % NS;
    size_t base = (size_t)t*3*ND;
    for (int idx = threadIdx.x; idx < 3*ND; idx += blockDim.x) {
        int k = idx / ND, i = idx % ND;
        int sp = s + k - 1;
        float val = (sp >= 0 && sp < NS) ? g_x[(size_t)(t + k - 1)*ND + i] : 0.0f;
        __nv_bfloat16 h,l; split_bf(val,h,l);
        g_xcb_h[base+idx]=h; g_xcb_l[base+idx]=l;
    }
}

__global__ void ln_kernel(const float* __restrict__ x, const float* __restrict__ g,
                          const float* __restrict__ b, float* __restrict__ out,
                          __nv_bfloat16* __restrict__ oh, __nv_bfloat16* __restrict__ ol){
    __shared__ float red[256];
    int r = blockIdx.x;
    const float* xr = x + (size_t)r*ND;
    int tid = threadIdx.x;
    float s = 0.f;
    for (int d = tid; d < ND; d += 256) s += xr[d];
    red[tid] = s; __syncthreads();
    for (int o = 128; o > 0; o >>= 1){ if (tid < o) red[tid] += red[tid+o]; __syncthreads(); }
    float mean = red[0] / (float)ND;
    __syncthreads();
    float vs = 0.f;
    for (int d = tid; d < ND; d += 256){ float dd = xr[d]-mean; vs += dd*dd; }
    red[tid] = vs; __syncthreads();
    for (int o = 128; o > 0; o >>= 1){ if (tid < o) red[tid] += red[tid+o]; __syncthreads(); }
    float rstd = rsqrtf(red[0]/(float)ND + 1e-5f);
    size_t base = (size_t)r*ND;
    for (int d = tid; d < ND; d += 256){
        float v = (xr[d]-mean)*rstd*g[d] + b[d];
        out[base+d] = v;
        __nv_bfloat16 h,l; split_bf(v,h,l);
        oh[base+d]=h; ol[base+d]=l;
    }
}

__global__ void zero_cnt_kernel(){
    if (threadIdx.x < NE) g_ecnt[threadIdx.x] = 0;
}

// router: softmax -> top2 -> compact lists + (slot, gate) records
__global__ void router_kernel(const float* __restrict__ h, const float* __restrict__ rw,
                              const float* __restrict__ rb){
    int t = blockIdx.x*blockDim.y + threadIdx.y;
    int lane = threadIdx.x;
    float a0=0.f,a1=0.f,a2=0.f,a3=0.f;
    const float* hr = h + (size_t)t*ND;
    for (int d = lane; d < ND; d += 32){
        float hv = hr[d];
        a0 += hv*rw[d*NE+0];
        a1 += hv*rw[d*NE+1];
        a2 += hv*rw[d*NE+2];
        a3 += hv*rw[d*NE+3];
    }
    #pragma unroll
    for (int o=16;o>0;o>>=1){
        a0 += __shfl_down_sync(0xffffffffu, a0, o);
        a1 += __shfl_down_sync(0xffffffffu, a1, o);
        a2 += __shfl_down_sync(0xffffffffu, a2, o);
        a3 += __shfl_down_sync(0xffffffffu, a3, o);
    }
    if (lane==0){
        float l[4]={a0+rb[0],a1+rb[1],a2+rb[2],a3+rb[3]};
        float lm = fmaxf(fmaxf(l[0],l[1]),fmaxf(l[2],l[3]));
        float p[4]; float sum=0.f;
        #pragma unroll
        for(int e=0;e<4;e++){ p[e]=expf(l[e]-lm); sum+=p[e]; }
        #pragma unroll
        for(int e=0;e<4;e++) p[e]/=sum;
        int i0=0;
        #pragma unroll
        for(int e=1;e<4;e++) if(p[e]>p[i0]) i0=e;
        int i1=-1;
        #pragma unroll
        for(int e=0;e<4;e++){ if(e==i0) continue; if(i1<0 || p[e]>p[i1]) i1=e; }
        float gs = p[i0]+p[i1];
        int pos0 = atomicAdd(&g_ecnt[i0], 1); g_eidx[i0*NT+pos0]=t;
        int pos1 = atomicAdd(&g_ecnt[i1], 1); g_eidx[i1*NT+pos1]=t;
        g_slot[2*t+0]  = i0*NT+pos0;
        g_slot[2*t+1]  = i1*NT+pos1;
        g_sgate[2*t+0] = p[i0]/gs;
        g_sgate[2*t+1] = p[i1]/gs;
    }
}

// combine: x[t] += g0*h2[slot0] + g1*h2[slot1]   (192 thr, float4)
__global__ void moe_combine_kernel(){
    int t = blockIdx.x;
    long long s0 = g_slot[2*t+0], s1 = g_slot[2*t+1];
    float w0 = g_sgate[2*t+0], w1 = g_sgate[2*t+1];
    const float4* a = (const float4*)(g_h2 + s0*ND);
    const float4* b = (const float4*)(g_h2 + s1*ND);
    float4* xp = (float4*)(g_x + (size_t)t*ND);
    int d = threadIdx.x;
    float4 xv = xp[d], av = a[d], bv = b[d];
    xv.x += w0*av.x + w1*bv.x;
    xv.y += w0*av.y + w1*bv.y;
    xv.z += w0*av.z + w1*bv.z;
    xv.w += w0*av.w + w1*bv.w;
    xp[d] = xv;
}

// ================= fused flash attention (fp32 f32x2) =================
#define FL_SMEM (25600*4)
__global__ void __launch_bounds__(256,1) flash_kernel(const float* __restrict__ qkv,
        __nv_bfloat16* __restrict__ oh, __nv_bfloat16* __restrict__ ol){
    extern __shared__ float fs[];
    float* Qs = fs;
    float* Ks = fs + 8448;
    float* Vs = fs + 12800;
    float* Ps = fs + 17152;

    int qb = blockIdx.x;
    int bh = blockIdx.y;
    int b = bh / NH, hh = bh - b*NH;
    int tid = threadIdx.x;
    int tx = tid & 15, ty = tid >> 4;
    int r0 = ty*8, c0 = tx*4;
    long long tbase = (long long)b*NS + qb*128;
    int qcol = hh*64, kcol = ND + hh*64, vcol = 2*ND + hh*64;

    for (int idx = tid; idx < 128*16; idx += 256){
        int row = idx >> 4, ds = (idx & 15)*4;
        float4 qv = *(const float4*)(qkv + (tbase+row)*NQKV + qcol + ds);
        Qs[(ds+0)*132+row] = qv.x*0.125f;
        Qs[(ds+1)*132+row] = qv.y*0.125f;
        Qs[(ds+2)*132+row] = qv.z*0.125f;
        Qs[(ds+3)*132+row] = qv.w*0.125f;
    }

    float m[8], l[8];
    unsigned long long oacc[8][2];
    #pragma unroll
    for (int i=0;i<8;i++){ m[i]=-1e30f; l[i]=0.f; oacc[i][0]=0ULL; oacc[i][1]=0ULL; }

    long long kvbase = (long long)b*NS;
    for (int kt=0; kt<16; kt++){
        __syncthreads();
        for (int idx = tid; idx < 64*16; idx += 256){
            int krow = idx >> 4, ds = (idx & 15)*4;
            long long grow = (kvbase + kt*64 + krow)*NQKV;
            float4 kv = *(const float4*)(qkv + grow + kcol + ds);
            Ks[(ds+0)*68+krow] = kv.x;
            Ks[(ds+1)*68+krow] = kv.y;
            Ks[(ds+2)*68+krow] = kv.z;
            Ks[(ds+3)*68+krow] = kv.w;
            float4 vv = *(const float4*)(qkv + grow + vcol + ds);
            *(float4*)(Vs + krow*68 + ds) = vv;
        }
        __syncthreads();

        unsigned long long sa[8][2];
        #pragma unroll
        for (int i=0;i<8;i++){ sa[i][0]=0ULL; sa[i][1]=0ULL; }
        #pragma unroll 4
        for (int d=0; d<64; d++){
            float av[8];
            *(float4*)&av[0] = *(const float4*)(Qs + d*132 + r0);
            *(float4*)&av[4] = *(const float4*)(Qs + d*132 + r0 + 4);
            unsigned long long k2[2];
            k2[0] = *(const unsigned long long*)(Ks + d*68 + c0);
            k2[1] = *(const unsigned long long*)(Ks + d*68 + c0 + 2);
            #pragma unroll
            for (int i=0;i<8;i++){
                unsigned long long ad; DUP2(ad, av[i]);
                FMA2(sa[i][0], ad, k2[0], sa[i][0]);
                FMA2(sa[i][1], ad, k2[1], sa[i][1]);
            }
        }

        #pragma unroll
        for (int i=0;i<8;i++){
            float s0,s1,s2,s3;
            UNP2(s0,s1, sa[i][0]);
            UNP2(s2,s3, sa[i][1]);
            float lm = fmaxf(fmaxf(s0,s1), fmaxf(s2,s3));
            #pragma unroll
            for (int ms=8; ms>0; ms>>=1)
                lm = fmaxf(lm, __shfl_xor_sync(0xffffffffu, lm, ms));
            float mnew = fmaxf(m[i], lm);
            float sc = expf(m[i]-mnew);
            float p0 = expf(s0-mnew), p1 = expf(s1-mnew);
            float p2 = expf(s2-mnew), p3 = expf(s3-mnew);
            float rs = (p0+p1)+(p2+p3);
            #pragma unroll
            for (int ms=8; ms>0; ms>>=1)
                rs += __shfl_xor_sync(0xffffffffu, rs, ms);
            l[i] = l[i]*sc + rs;
            m[i] = mnew;
            unsigned long long scd; DUP2(scd, sc);
            MUL2(oacc[i][0], oacc[i][0], scd);
            MUL2(oacc[i][1], oacc[i][1], scd);
            Ps[(c0+0)*132 + r0+i] = p0;
            Ps[(c0+1)*132 + r0+i] = p1;
            Ps[(c0+2)*132 + r0+i] = p2;
            Ps[(c0+3)*132 + r0+i] = p3;
        }
        __syncthreads();

        #pragma unroll 4
        for (int k=0; k<64; k++){
            float pv[8];
            *(float4*)&pv[0] = *(const float4*)(Ps + k*132 + r0);
            *(float4*)&pv[4] = *(const float4*)(Ps + k*132 + r0 + 4);
            unsigned long long v2[2];
            v2[0] = *(const unsigned long long*)(Vs + k*68 + c0);
            v2[1] = *(const unsigned long long*)(Vs + k*68 + c0 + 2);
            #pragma unroll
            for (int i=0;i<8;i++){
                unsigned long long pd; DUP2(pd, pv[i]);
                FMA2(oacc[i][0], pd, v2[0], oacc[i][0]);
                FMA2(oacc[i][1], pd, v2[1], oacc[i][1]);
            }
        }
    }

    #pragma unroll
    for (int i=0;i<8;i++){
        float inv = 1.0f / l[i];
        float o0,o1,o2,o3;
        UNP2(o0,o1, oacc[i][0]);
        UNP2(o2,o3, oacc[i][1]);
        o0*=inv; o1*=inv; o2*=inv; o3*=inv;
        long long ixb = (tbase + r0 + i)*ND + hh*64 + c0;
        __nv_bfloat16 hb,lb;
        split_bf(o0,hb,lb); oh[ixb+0]=hb; ol[ixb+0]=lb;
        split_bf(o1,hb,lb); oh[ixb+1]=hb; ol[ixb+1]=lb;
        split_bf(o2,hb,lb); oh[ixb+2]=hb; ol[ixb+2]=lb;
        split_bf(o3,hb,lb); oh[ixb+3]=hb; ol[ixb+3]=lb;
    }
}

// ================= mma.sync bf16-split GEMM (R6 double-buffer core, z-batched) =====
#define TG_SMEM (2*4*128*40*2)

__global__ void __launch_bounds__(256,1) tgemm_kernel(
    const __nv_bfloat16* __restrict__ Ah, const __nv_bfloat16* __restrict__ Al, int lda, long long zA,
    const __nv_bfloat16* __restrict__ Bh, const __nv_bfloat16* __restrict__ Bl, int ldb, long long zB,
    float* __restrict__ C, int ldc,
    __nv_bfloat16* __restrict__ Oh, __nv_bfloat16* __restrict__ Ol, int ldo, long long zC,
    int M, int N, int K,
    const float* __restrict__ bias, int zbias, int act, int accum,
    const int* __restrict__ gidx, const int* __restrict__ gcount, int zg, int gatherA)
{
    extern __shared__ __nv_bfloat16 sm[];
    int z = blockIdx.z;
    Ah += z*zA; Al += z*zA;
    Bh += z*zB; Bl += z*zB;
    if (C){ C += z*zC; }
    if (Oh){ Oh += z*zC; Ol += z*zC; }
    if (bias) bias += (long long)z*zbias;
    if (gidx && zg){ gidx += (long long)z*zg; gcount += z; }

    int count = gcount ? *gcount : M;
    int m0 = blockIdx.y*128, n0 = blockIdx.x*128;
    if (count <= 0 || m0 >= count) return;

    int tid = threadIdx.x, wid = tid>>5, lane = tid&31;
    int wm = (wid>>2)*64, wn = (wid&3)*32;
    uint32_t smb = smem_u32(sm);

    float acc[4][4][4];
    #pragma unroll
    for (int mi=0;mi<4;mi++)
        #pragma unroll
        for (int ni=0;ni<4;ni++)
            #pragma unroll
            for (int f=0;f<4;f++) acc[mi][ni][f]=0.f;

    unsigned long long stA[2][4], stB[2][4];

    auto ldg_tile = [&](int kt){
        int kb = kt*32;
        #pragma unroll
        for (int u=0;u<4;u++){
            int c = tid + u*256;
            int row = c>>3, kc = (c&7)*4;
            int ar = m0+row; ar = ar<count ? ar : count-1;
            long long arow = gatherA ? gidx[ar] : ar;
            long long goff = arow*(long long)lda + kb + kc;
            stA[0][u] = *(const unsigned long long*)(Ah+goff);
            stA[1][u] = *(const unsigned long long*)(Al+goff);
            long long boff = (long long)(n0+row)*ldb + kb + kc;
            stB[0][u] = *(const unsigned long long*)(Bh+boff);
            stB[1][u] = *(const unsigned long long*)(Bl+boff);
        }
    };
    auto sts_tile = [&](int buf){
        __nv_bfloat16* base = sm + buf*20480;
        #pragma unroll
        for (int u=0;u<4;u++){
            int c = tid + u*256;
            int row = c>>3, kc = (c&7)*4;
            *(unsigned long long*)(base + row*40 + kc)         = stA[0][u];
            *(unsigned long long*)(base + 5120 + row*40 + kc)  = stA[1][u];
            *(unsigned long long*)(base + 10240 + row*40 + kc) = stB[0][u];
            *(unsigned long long*)(base + 15360 + row*40 + kc) = stB[1][u];
        }
    };

    ldg_tile(0);
    sts_tile(0);
    __syncthreads();

    int KT = K >> 5;
    int buf = 0;
    for (int kt=0; kt<KT; kt++){
        bool has_next = (kt+1) < KT;
        if (has_next) ldg_tile(kt+1);

        uint32_t bufb = smb + (uint32_t)buf*40960u;
        #pragma unroll
        for (int ks=0; ks<2; ks++){
            uint32_t ah[4][4], al[4][4];
            int arow_l = (lane&7) + ((lane>>3)&1)*8;
            int akcol  = ks*16 + (lane>>4)*8;
            #pragma unroll
            for (int mi=0;mi<4;mi++){
                uint32_t off = (uint32_t)((wm + mi*16 + arow_l)*80 + akcol*2);
                LDSM_X4(ah[mi][0],ah[mi][1],ah[mi][2],ah[mi][3], bufb + off);
                LDSM_X4(al[mi][0],al[mi][1],al[mi][2],al[mi][3], bufb + 10240u + off);
            }
            uint32_t bh[4][2], bl[4][2];
            int brow_l = lane&7;
            int bkcol  = ks*16 + ((lane>>3)&1)*8;
            #pragma unroll
            for (int ni=0;ni<4;ni++){
                uint32_t off = (uint32_t)((wn + ni*8 + brow_l)*80 + bkcol*2);
                LDSM_X2(bh[ni][0],bh[ni][1], bufb + 20480u + off);
                LDSM_X2(bl[ni][0],bl[ni][1], bufb + 30720u + off);
            }
            #pragma unroll
            for (int mi=0;mi<4;mi++)
                #pragma unroll
                for (int ni=0;ni<4;ni++){
                    MMA16816(acc[mi][ni], ah[mi], bh[ni]);
                    MMA16816(acc[mi][ni], ah[mi], bl[ni]);
                    MMA16816(acc[mi][ni], al[mi], bh[ni]);
                }
        }

        if (has_next){
            __syncthreads();
            sts_tile(buf^1);
            __syncthreads();
            buf ^= 1;
        }
    }

    // ---- epilogue (compact rows; no scatter) ----
    #pragma unroll
    for (int mi=0;mi<4;mi++){
        #pragma unroll
        for (int half=0; half<2; half++){
            int m = m0 + wm + mi*16 + (lane>>2) + half*8;
            if (m >= count) continue;
            #pragma unroll
            for (int ni=0;ni<4;ni++){
                int n = n0 + wn + ni*8 + (lane&3)*2;
                float v0 = acc[mi][ni][half*2+0];
                float v1 = acc[mi][ni][half*2+1];
                if (bias){ v0 += bias[n]; v1 += bias[n+1]; }
                if (act){ v0 = gelu_f(v0); v1 = gelu_f(v1); }
                if (C){
                    long long ix = (long long)m*ldc + n;
                    if (accum){ C[ix] += v0; C[ix+1] += v1; }
                    else      { C[ix]  = v0; C[ix+1]  = v1; }
                }
                if (Oh){
                    long long ix = (long long)m*ldo + n;
                    __nv_bfloat16 h0,l0,h1,l1;
                    split_bf(v0,h0,l0); split_bf(v1,h1,l1);
                    Oh[ix]=h0; Ol[ix]=l0; Oh[ix+1]=h1; Ol[ix+1]=l1;
                }
            }
        }
    }
}

struct TArg {
    const __nv_bfloat16 *Ah,*Al; int lda; long long zA;
    const __nv_bfloat16 *Bh,*Bl; int ldb; long long zB;
    float* C; int ldc;
    __nv_bfloat16 *Oh,*Ol; int ldo; long long zC;
    int M,N,K,batch;
    const float* bias; int zbias; int act; int accum;
    const int* gidx; const int* gcnt; int zg; int gA;
};
static void launch_t(const TArg& a){
    dim3 grid((unsigned)(a.N/128), (unsigned)((a.M+127)/128), (unsigned)a.batch);
    tgemm_kernel<<<grid,256,TG_SMEM>>>(a.Ah,a.Al,a.lda,a.zA, a.Bh,a.Bl,a.ldb,a.zB,
        a.C,a.ldc, a.Oh,a.Ol,a.ldo,a.zC, a.M,a.N,a.K,
        a.bias,a.zbias,a.act,a.accum, a.gidx,a.gcnt,a.zg,a.gA);
}

extern "C" void kernel_launch(void* const* d_in, const int* in_sizes, int n_in,
                              void* d_out, int out_size)
{
    (void)in_sizes; (void)n_in; (void)out_size;
    const int*   text  = (const int*)  d_in[0];
    const float* embed = (const float*)d_in[1];
    const float* conv_w= (const float*)d_in[2];
    const float* conv_b= (const float*)d_in[3];
    const float* Wq    = (const float*)d_in[4];
    const float* bq    = (const float*)d_in[5];
    const float* Wk    = (const float*)d_in[6];
    const float* bk    = (const float*)d_in[7];
    const float* Wv    = (const float*)d_in[8];
    const float* bv    = (const float*)d_in[9];
    const float* Wo    = (const float*)d_in[10];
    const float* bo    = (const float*)d_in[11];
    const float* rw    = (const float*)d_in[12];
    const float* rb    = (const float*)d_in[13];
    const float* ew1   = (const float*)d_in[14];
    const float* eb1   = (const float*)d_in[15];
    const float* ew2   = (const float*)d_in[16];
    const float* eb2   = (const float*)d_in[17];
    const float* ln1g  = (const float*)d_in[18];
    const float* ln1b  = (const float*)d_in[19];
    const float* ln2g  = (const float*)d_in[20];
    const float* ln2b  = (const float*)d_in[21];
    const float* lnfg  = (const float*)d_in[22];
    const float* lnfb  = (const float*)d_in[23];
    const float* outw  = (const float*)d_in[24];
    const float* outb  = (const float*)d_in[25];
    float* out = (float*)d_out;

    cudaFuncSetAttribute(tgemm_kernel, cudaFuncAttributeMaxDynamicSharedMemorySize, TG_SMEM);
    cudaFuncSetAttribute(flash_kernel, cudaFuncAttributeMaxDynamicSharedMemorySize, FL_SMEM);

    float *x,*h,*qkv,*h2,*bqkv;
    int *eidx,*ecnt;
    cudaGetSymbolAddress((void**)&x,  g_x);
    cudaGetSymbolAddress((void**)&h,  g_h);
    cudaGetSymbolAddress((void**)&qkv, g_qkv);
    cudaGetSymbolAddress((void**)&h2, g_h2);
    cudaGetSymbolAddress((void**)&bqkv, g_bqkv);
    cudaGetSymbolAddress((void**)&eidx, g_eidx);
    cudaGetSymbolAddress((void**)&ecnt, g_ecnt);

    __nv_bfloat16 *hbh,*hbl,*obh,*obl,*xch,*xcl,*h1h,*h1l;
    __nv_bfloat16 *wch,*wcl,*wqkvh,*wqkvl,*woh,*wol,*w1h,*w1l,*w2h,*w2l,*wouth,*woutl;
    cudaGetSymbolAddress((void**)&hbh, g_hb_h);  cudaGetSymbolAddress((void**)&hbl, g_hb_l);
    cudaGetSymbolAddress((void**)&obh, g_ob_h);  cudaGetSymbolAddress((void**)&obl, g_ob_l);
    cudaGetSymbolAddress((void**)&xch, g_xcb_h); cudaGetSymbolAddress((void**)&xcl, g_xcb_l);
    cudaGetSymbolAddress((void**)&h1h, g_h1b_h); cudaGetSymbolAddress((void**)&h1l, g_h1b_l);
    cudaGetSymbolAddress((void**)&wch, g_wcT_h); cudaGetSymbolAddress((void**)&wcl, g_wcT_l);
    cudaGetSymbolAddress((void**)&wqkvh, g_wqkvT_h); cudaGetSymbolAddress((void**)&wqkvl, g_wqkvT_l);
    cudaGetSymbolAddress((void**)&woh, g_woT_h); cudaGetSymbolAddress((void**)&wol, g_woT_l);
    cudaGetSymbolAddress((void**)&w1h, g_w1T_h); cudaGetSymbolAddress((void**)&w1l, g_w1T_l);
    cudaGetSymbolAddress((void**)&w2h, g_w2T_h); cudaGetSymbolAddress((void**)&w2l, g_w2T_l);
    cudaGetSymbolAddress((void**)&wouth, g_woutT_h); cudaGetSymbolAddress((void**)&woutl, g_woutT_l);

    const long long LQKV = (long long)NQKV*ND;
    const long long LDD  = (long long)ND*ND;

    // ---- weight repack/split ----
    convw_kernel<<<(ND*3*ND+255)/256,256>>>(conv_w);
    wtrans_kernel<<<dim3(ND/32,ND/32,NL), dim3(32,8)>>>(Wq, wqkvh,               wqkvl,               ND, ND, LQKV);
    wtrans_kernel<<<dim3(ND/32,ND/32,NL), dim3(32,8)>>>(Wk, wqkvh+(size_t)ND*ND, wqkvl+(size_t)ND*ND, ND, ND, LQKV);
    wtrans_kernel<<<dim3(ND/32,ND/32,NL), dim3(32,8)>>>(Wv, wqkvh+(size_t)2*ND*ND, wqkvl+(size_t)2*ND*ND, ND, ND, LQKV);
    wtrans_kernel<<<dim3(ND/32,ND/32,NL), dim3(32,8)>>>(Wo, woh, wol, ND, ND, LDD);
    wtrans_kernel<<<dim3(NF/32,ND/32,NL*NE), dim3(32,8)>>>(ew1, w1h, w1l, ND, NF, (long long)ND*NF);
    wtrans_kernel<<<dim3(ND/32,NF/32,NL*NE), dim3(32,8)>>>(ew2, w2h, w2l, NF, ND, (long long)NF*ND);
    wtrans_kernel<<<dim3(NV/32,ND/32,1), dim3(32,8)>>>(outw, wouth, woutl, ND, NV, (long long)ND*NV);
    bpack_kernel<<<(NL*NQKV+255)/256,256>>>(bq, bk, bv);

    // ---- tokenizer ----
    embed_kernel<<<NT,256>>>(text, embed);
    xcat_kernel<<<NT,256>>>();
    {   TArg a = {xch,xcl,3*ND,0, wch,wcl,3*ND,0, x,ND, nullptr,nullptr,0,0,
                  NT,ND,3*ND,1, conv_b,0,1, 1, nullptr,nullptr,0,0};
        launch_t(a); }

    for (int i=0;i<NL;i++){
        // ---- attention ----
        ln_kernel<<<NT,256>>>(x, ln1g+(size_t)i*ND, ln1b+(size_t)i*ND, h, hbh, hbl);
        {   TArg a = {hbh,hbl,ND,0, wqkvh+(size_t)i*LQKV, wqkvl+(size_t)i*LQKV, ND,0, qkv,NQKV,
                      nullptr,nullptr,0,0, NT,NQKV,ND,1, bqkv+(size_t)i*NQKV,0,0, 0, nullptr,nullptr,0,0};
            launch_t(a); }
        flash_kernel<<<dim3(NS/128, NB*NH),256,FL_SMEM>>>(qkv, obh, obl);
        {   TArg a = {obh,obl,ND,0, woh+(size_t)i*LDD, wol+(size_t)i*LDD, ND,0, x,ND,
                      nullptr,nullptr,0,0, NT,ND,ND,1, bo+(size_t)i*ND,0,0, 1, nullptr,nullptr,0,0};
            launch_t(a); }

        // ---- MoE (top-2, batched over experts via grid.z) ----
        ln_kernel<<<NT,256>>>(x, ln2g+(size_t)i*ND, ln2b+(size_t)i*ND, h, hbh, hbl);
        zero_cnt_kernel<<<1,32>>>();
        router_kernel<<<NT/4, dim3(32,4)>>>(h, rw+(size_t)i*ND*NE, rb+(size_t)i*NE);
        // h1[e] = gelu(h[eidx[e]] @ w1[e] + b1[e])   — one launch, z=expert
        {   TArg a = {hbh,hbl,ND,0,
                      w1h+(size_t)i*NE*NF*ND, w1l+(size_t)i*NE*NF*ND, ND,(long long)NF*ND,
                      nullptr,0,
                      h1h,h1l,NF,(long long)NT*NF,
                      NT,NF,ND,NE,
                      eb1+(size_t)i*NE*NF, NF, 1, 0,
                      eidx, ecnt, NT, 1};
            launch_t(a); }
        // h2[e] = h1[e] @ w2[e] + b2[e]   (compact, no gate) — one launch, z=expert
        {   TArg a = {h1h,h1l,NF,(long long)NT*NF,
                      w2h+(size_t)i*NE*ND*NF, w2l+(size_t)i*NE*ND*NF, NF,(long long)ND*NF,
                      h2,ND,
                      nullptr,nullptr,0,(long long)NT*ND,
                      NT,ND,NF,NE,
                      eb2+(size_t)i*NE*ND, ND, 0, 0,
                      eidx, ecnt, NT, 0};
            launch_t(a); }
        moe_combine_kernel<<<NT,192>>>();
    }

    // ---- final LN + output projection ----
    ln_kernel<<<NT,256>>>(x, lnfg, lnfb, h, hbh, hbl);
    {   TArg a = {hbh,hbl,ND,0, wouth,woutl,ND,0, out,NV, nullptr,nullptr,0,0,
                  NT,NV,ND,1, outb,0,0, 0, nullptr,nullptr,0,0};
        launch_t(a); }
}

// round 13
// speedup vs baseline: 1.0354x; 1.0354x over previous
#include <cuda_runtime.h>
#include <cuda_bf16.h>
#include <math.h>
#include <stdint.h>

#define NL 4
#define NB 4
#define NS 1024
#define ND 768
#define NF 3072
#define NE 4
#define NV 256
#define NH 12
#define NDH 64
#define NT (NB*NS)
#define NQKV 2304

// ================= packed f32x2 helpers =================
#define FMA2(d,a,b,c) asm("fma.rn.f32x2 %0, %1, %2, %3;" : "=l"(d) : "l"(a), "l"(b), "l"(c))
#define MUL2(d,a,b)   asm("mul.rn.f32x2 %0, %1, %2;" : "=l"(d) : "l"(a), "l"(b))
#define DUP2(d,s)     asm("mov.b64 %0, {%1, %1};" : "=l"(d) : "f"(s))
#define UNP2(lo,hi,v) asm("mov.b64 {%0, %1}, %2;" : "=f"(lo), "=f"(hi) : "l"(v))

__device__ __forceinline__ uint32_t smem_u32(const void* p){
    uint32_t a;
    asm("{ .reg .u64 t; cvta.to.shared.u64 t, %1; cvt.u32.u64 %0, t; }" : "=r"(a) : "l"(p));
    return a;
}

// ldmatrix / mma wrappers (sm_80+, OK on compute_103)
#define LDSM_X4(r0,r1,r2,r3,addr) \
    asm volatile("ldmatrix.sync.aligned.m8n8.x4.shared.b16 {%0,%1,%2,%3}, [%4];" \
        : "=r"(r0),"=r"(r1),"=r"(r2),"=r"(r3) : "r"(addr))
#define LDSM_X2(r0,r1,addr) \
    asm volatile("ldmatrix.sync.aligned.m8n8.x2.shared.b16 {%0,%1}, [%2];" \
        : "=r"(r0),"=r"(r1) : "r"(addr))
#define MMA16816(d,a,b) \
    asm volatile("mma.sync.aligned.m16n8k16.row.col.f32.bf16.bf16.f32 " \
        "{%0,%1,%2,%3}, {%4,%5,%6,%7}, {%8,%9}, {%0,%1,%2,%3};" \
        : "+f"((d)[0]),"+f"((d)[1]),"+f"((d)[2]),"+f"((d)[3]) \
        : "r"((a)[0]),"r"((a)[1]),"r"((a)[2]),"r"((a)[3]), "r"((b)[0]),"r"((b)[1]))

// ================= scratch =================
__device__ float g_x[NT*ND];
__device__ float g_h[NT*ND];
__device__ float g_qkv[(size_t)NT*NQKV];
__device__ float g_h2[(size_t)NE*NT*ND];      // compact per-expert MoE outputs
__device__ float g_bqkv[NL*NQKV];
__device__ float g_sgate[NT*2];               // top-2 gates per token
__device__ int   g_slot[NT*2];                // e*NT+pos per token
__device__ int   g_eidx[NE*NT];
__device__ int   g_ecnt[NE];

__device__ __nv_bfloat16 g_hb_h[NT*ND],  g_hb_l[NT*ND];
__device__ __nv_bfloat16 g_ob_h[NT*ND],  g_ob_l[NT*ND];
__device__ __nv_bfloat16 g_xcb_h[NT*3*ND], g_xcb_l[NT*3*ND];
__device__ __nv_bfloat16 g_h1b_h[(size_t)NE*NT*NF], g_h1b_l[(size_t)NE*NT*NF];
__device__ __nv_bfloat16 g_wcT_h[ND*3*ND], g_wcT_l[ND*3*ND];
__device__ __nv_bfloat16 g_wqkvT_h[NL*NQKV*ND], g_wqkvT_l[NL*NQKV*ND];
__device__ __nv_bfloat16 g_woT_h[NL*ND*ND], g_woT_l[NL*ND*ND];
__device__ __nv_bfloat16 g_w1T_h[NL*NE*NF*ND], g_w1T_l[NL*NE*NF*ND];
__device__ __nv_bfloat16 g_w2T_h[NL*NE*ND*NF], g_w2T_l[NL*NE*ND*NF];
__device__ __nv_bfloat16 g_woutT_h[NV*ND], g_woutT_l[NV*ND];

__device__ __forceinline__ float gelu_f(float x){
    const float c = 0.7978845608028654f;
    return 0.5f*x*(1.0f + tanhf(c*(x + 0.044715f*x*x*x)));
}
__device__ __forceinline__ void split_bf(float v, __nv_bfloat16& h, __nv_bfloat16& l){
    h = __float2bfloat16(v);
    l = __float2bfloat16(v - __bfloat162float(h));
}

// ================= small kernels =================
__global__ void embed_kernel(const int* __restrict__ text, const float* __restrict__ emb){
    int t = blockIdx.x;
    int tok = text[t];
    const float* src = emb + (size_t)tok*ND;
    float* dst = g_x + (size_t)t*ND;
    for (int d = threadIdx.x; d < ND; d += blockDim.x) dst[d] = src[d];
}

__global__ void convw_kernel(const float* __restrict__ w){
    int idx = blockIdx.x*blockDim.x + threadIdx.x;
    if (idx >= ND*3*ND) return;
    int o = idx / (3*ND);
    int r = idx % (3*ND);
    int k = r / ND, i = r % ND;
    float v = w[((size_t)o*ND + i)*3 + k];
    split_bf(v, g_wcT_h[idx], g_wcT_l[idx]);
}

// vectorized transpose+split: in [K][N] (z-stride K*N) -> out [N][K] (z-stride ozs)
// tiles: 64 (K) x 32 (N); packed bf16x2 cvt; 16B stores. Requires K%64==0, N%32==0.
__global__ void wtrans_kernel(const float* __restrict__ in, __nv_bfloat16* __restrict__ hi,
                              __nv_bfloat16* __restrict__ lo, int K, int N, long long ozs){
    __shared__ float t[64][33];
    size_t zi = (size_t)blockIdx.z*K*N;
    size_t zo = (size_t)blockIdx.z*ozs;
    int n0 = blockIdx.x*32, k0 = blockIdx.y*64;
    int tid = threadIdx.x;   // 256
    #pragma unroll
    for (int u=0;u<2;u++){
        int c = tid + u*256;         // 0..511
        int kr = c >> 3;             // 0..63
        int nc = (c & 7) * 4;        // 0..28
        float4 v = *(const float4*)(in + zi + (size_t)(k0+kr)*N + n0 + nc);
        t[kr][nc+0]=v.x; t[kr][nc+1]=v.y; t[kr][nc+2]=v.z; t[kr][nc+3]=v.w;
    }
    __syncthreads();
    int nr = tid >> 3;               // 0..31
    int kc = (tid & 7) * 8;          // 0..56
    float v[8];
    #pragma unroll
    for (int j=0;j<8;j++) v[j] = t[kc+j][nr];
    uint32_t hp[4], lp[4];
    #pragma unroll
    for (int j=0;j<4;j++){
        uint32_t ph;
        asm("cvt.rn.bf16x2.f32 %0, %1, %2;" : "=r"(ph) : "f"(v[2*j+1]), "f"(v[2*j]));
        hp[j] = ph;
        float h0 = __uint_as_float(ph << 16);
        float h1 = __uint_as_float(ph & 0xffff0000u);
        float l0 = v[2*j]   - h0;
        float l1 = v[2*j+1] - h1;
        uint32_t pl;
        asm("cvt.rn.bf16x2.f32 %0, %1, %2;" : "=r"(pl) : "f"(l1), "f"(l0));
        lp[j] = pl;
    }
    size_t oo = zo + (size_t)(n0+nr)*K + k0 + kc;   // element offset; *2 bytes, 16B aligned
    *(uint4*)((char*)hi + oo*2) = *(const uint4*)hp;
    *(uint4*)((char*)lo + oo*2) = *(const uint4*)lp;
}

__global__ void bpack_kernel(const float* __restrict__ bq, const float* __restrict__ bk,
                             const float* __restrict__ bv){
    int idx = blockIdx.x*blockDim.x + threadIdx.x;
    if (idx >= NL*NQKV) return;
    int layer = idx / NQKV, c = idx % NQKV;
    float v;
    if (c < ND)            v = bq[layer*ND + c];
    else if (c < 2*ND)     v = bk[layer*ND + c - ND];
    else                   v = bv[layer*ND + c - 2*ND];
    g_bqkv[idx] = v;
}

__global__ void xcat_kernel(){
    int t = blockIdx.x;
    int s = t % NS;
    size_t base = (size_t)t*3*ND;
    for (int idx = threadIdx.x; idx < 3*ND; idx += blockDim.x) {
        int k = idx / ND, i = idx % ND;
        int sp = s + k - 1;
        float val = (sp >= 0 && sp < NS) ? g_x[(size_t)(t + k - 1)*ND + i] : 0.0f;
        __nv_bfloat16 h,l; split_bf(val,h,l);
        g_xcb_h[base+idx]=h; g_xcb_l[base+idx]=l;
    }
}

__global__ void ln_kernel(const float* __restrict__ x, const float* __restrict__ g,
                          const float* __restrict__ b, float* __restrict__ out,
                          __nv_bfloat16* __restrict__ oh, __nv_bfloat16* __restrict__ ol){
    __shared__ float red[256];
    int r = blockIdx.x;
    const float* xr = x + (size_t)r*ND;
    int tid = threadIdx.x;
    float s = 0.f;
    for (int d = tid; d < ND; d += 256) s += xr[d];
    red[tid] = s; __syncthreads();
    for (int o = 128; o > 0; o >>= 1){ if (tid < o) red[tid] += red[tid+o]; __syncthreads(); }
    float mean = red[0] / (float)ND;
    __syncthreads();
    float vs = 0.f;
    for (int d = tid; d < ND; d += 256){ float dd = xr[d]-mean; vs += dd*dd; }
    red[tid] = vs; __syncthreads();
    for (int o = 128; o > 0; o >>= 1){ if (tid < o) red[tid] += red[tid+o]; __syncthreads(); }
    float rstd = rsqrtf(red[0]/(float)ND + 1e-5f);
    size_t base = (size_t)r*ND;
    for (int d = tid; d < ND; d += 256){
        float v = (xr[d]-mean)*rstd*g[d] + b[d];
        out[base+d] = v;
        __nv_bfloat16 h,l; split_bf(v,h,l);
        oh[base+d]=h; ol[base+d]=l;
    }
}

__global__ void zero_cnt_kernel(){
    if (threadIdx.x < NE) g_ecnt[threadIdx.x] = 0;
}

// router: softmax -> top2 -> compact lists + (slot, gate) records
__global__ void router_kernel(const float* __restrict__ h, const float* __restrict__ rw,
                              const float* __restrict__ rb){
    int t = blockIdx.x*blockDim.y + threadIdx.y;
    int lane = threadIdx.x;
    float a0=0.f,a1=0.f,a2=0.f,a3=0.f;
    const float* hr = h + (size_t)t*ND;
    for (int d = lane; d < ND; d += 32){
        float hv = hr[d];
        a0 += hv*rw[d*NE+0];
        a1 += hv*rw[d*NE+1];
        a2 += hv*rw[d*NE+2];
        a3 += hv*rw[d*NE+3];
    }
    #pragma unroll
    for (int o=16;o>0;o>>=1){
        a0 += __shfl_down_sync(0xffffffffu, a0, o);
        a1 += __shfl_down_sync(0xffffffffu, a1, o);
        a2 += __shfl_down_sync(0xffffffffu, a2, o);
        a3 += __shfl_down_sync(0xffffffffu, a3, o);
    }
    if (lane==0){
        float l[4]={a0+rb[0],a1+rb[1],a2+rb[2],a3+rb[3]};
        float lm = fmaxf(fmaxf(l[0],l[1]),fmaxf(l[2],l[3]));
        float p[4]; float sum=0.f;
        #pragma unroll
        for(int e=0;e<4;e++){ p[e]=expf(l[e]-lm); sum+=p[e]; }
        #pragma unroll
        for(int e=0;e<4;e++) p[e]/=sum;
        int i0=0;
        #pragma unroll
        for(int e=1;e<4;e++) if(p[e]>p[i0]) i0=e;
        int i1=-1;
        #pragma unroll
        for(int e=0;e<4;e++){ if(e==i0) continue; if(i1<0 || p[e]>p[i1]) i1=e; }
        float gs = p[i0]+p[i1];
        int pos0 = atomicAdd(&g_ecnt[i0], 1); g_eidx[i0*NT+pos0]=t;
        int pos1 = atomicAdd(&g_ecnt[i1], 1); g_eidx[i1*NT+pos1]=t;
        g_slot[2*t+0]  = i0*NT+pos0;
        g_slot[2*t+1]  = i1*NT+pos1;
        g_sgate[2*t+0] = p[i0]/gs;
        g_sgate[2*t+1] = p[i1]/gs;
    }
}

// combine: x[t] += g0*h2[slot0] + g1*h2[slot1]
__global__ void moe_combine_kernel(){
    int t = blockIdx.x;
    long long s0 = g_slot[2*t+0], s1 = g_slot[2*t+1];
    float w0 = g_sgate[2*t+0], w1 = g_sgate[2*t+1];
    const float4* a = (const float4*)(g_h2 + s0*ND);
    const float4* b = (const float4*)(g_h2 + s1*ND);
    float4* xp = (float4*)(g_x + (size_t)t*ND);
    int d = threadIdx.x;
    float4 xv = xp[d], av = a[d], bv = b[d];
    xv.x += w0*av.x + w1*bv.x;
    xv.y += w0*av.y + w1*bv.y;
    xv.z += w0*av.z + w1*bv.z;
    xv.w += w0*av.w + w1*bv.w;
    xp[d] = xv;
}

// ================= fused flash attention (fp32 f32x2), 2 CTAs/SM =================
#define FL_SMEM (25600*4)
__global__ void __launch_bounds__(256,2) flash_kernel(const float* __restrict__ qkv,
        __nv_bfloat16* __restrict__ oh, __nv_bfloat16* __restrict__ ol){
    extern __shared__ float fs[];
    float* Qs = fs;
    float* Ks = fs + 8448;
    float* Vs = fs + 12800;
    float* Ps = fs + 17152;

    int qb = blockIdx.x;
    int bh = blockIdx.y;
    int b = bh / NH, hh = bh - b*NH;
    int tid = threadIdx.x;
    int tx = tid & 15, ty = tid >> 4;
    int r0 = ty*8, c0 = tx*4;
    long long tbase = (long long)b*NS + qb*128;
    int qcol = hh*64, kcol = ND + hh*64, vcol = 2*ND + hh*64;

    for (int idx = tid; idx < 128*16; idx += 256){
        int row = idx >> 4, ds = (idx & 15)*4;
        float4 qv = *(const float4*)(qkv + (tbase+row)*NQKV + qcol + ds);
        Qs[(ds+0)*132+row] = qv.x*0.125f;
        Qs[(ds+1)*132+row] = qv.y*0.125f;
        Qs[(ds+2)*132+row] = qv.z*0.125f;
        Qs[(ds+3)*132+row] = qv.w*0.125f;
    }

    float m[8], l[8];
    unsigned long long oacc[8][2];
    #pragma unroll
    for (int i=0;i<8;i++){ m[i]=-1e30f; l[i]=0.f; oacc[i][0]=0ULL; oacc[i][1]=0ULL; }

    long long kvbase = (long long)b*NS;
    for (int kt=0; kt<16; kt++){
        __syncthreads();
        for (int idx = tid; idx < 64*16; idx += 256){
            int krow = idx >> 4, ds = (idx & 15)*4;
            long long grow = (kvbase + kt*64 + krow)*NQKV;
            float4 kv = *(const float4*)(qkv + grow + kcol + ds);
            Ks[(ds+0)*68+krow] = kv.x;
            Ks[(ds+1)*68+krow] = kv.y;
            Ks[(ds+2)*68+krow] = kv.z;
            Ks[(ds+3)*68+krow] = kv.w;
            float4 vv = *(const float4*)(qkv + grow + vcol + ds);
            *(float4*)(Vs + krow*68 + ds) = vv;
        }
        __syncthreads();

        unsigned long long sa[8][2];
        #pragma unroll
        for (int i=0;i<8;i++){ sa[i][0]=0ULL; sa[i][1]=0ULL; }
        #pragma unroll 4
        for (int d=0; d<64; d++){
            float av[8];
            *(float4*)&av[0] = *(const float4*)(Qs + d*132 + r0);
            *(float4*)&av[4] = *(const float4*)(Qs + d*132 + r0 + 4);
            unsigned long long k2[2];
            k2[0] = *(const unsigned long long*)(Ks + d*68 + c0);
            k2[1] = *(const unsigned long long*)(Ks + d*68 + c0 + 2);
            #pragma unroll
            for (int i=0;i<8;i++){
                unsigned long long ad; DUP2(ad, av[i]);
                FMA2(sa[i][0], ad, k2[0], sa[i][0]);
                FMA2(sa[i][1], ad, k2[1], sa[i][1]);
            }
        }

        #pragma unroll
        for (int i=0;i<8;i++){
            float s0,s1,s2,s3;
            UNP2(s0,s1, sa[i][0]);
            UNP2(s2,s3, sa[i][1]);
            float lm = fmaxf(fmaxf(s0,s1), fmaxf(s2,s3));
            #pragma unroll
            for (int ms=8; ms>0; ms>>=1)
                lm = fmaxf(lm, __shfl_xor_sync(0xffffffffu, lm, ms));
            float mnew = fmaxf(m[i], lm);
            float sc = expf(m[i]-mnew);
            float p0 = expf(s0-mnew), p1 = expf(s1-mnew);
            float p2 = expf(s2-mnew), p3 = expf(s3-mnew);
            float rs = (p0+p1)+(p2+p3);
            #pragma unroll
            for (int ms=8; ms>0; ms>>=1)
                rs += __shfl_xor_sync(0xffffffffu, rs, ms);
            l[i] = l[i]*sc + rs;
            m[i] = mnew;
            unsigned long long scd; DUP2(scd, sc);
            MUL2(oacc[i][0], oacc[i][0], scd);
            MUL2(oacc[i][1], oacc[i][1], scd);
            Ps[(c0+0)*132 + r0+i] = p0;
            Ps[(c0+1)*132 + r0+i] = p1;
            Ps[(c0+2)*132 + r0+i] = p2;
            Ps[(c0+3)*132 + r0+i] = p3;
        }
        __syncthreads();

        #pragma unroll 4
        for (int k=0; k<64; k++){
            float pv[8];
            *(float4*)&pv[0] = *(const float4*)(Ps + k*132 + r0);
            *(float4*)&pv[4] = *(const float4*)(Ps + k*132 + r0 + 4);
            unsigned long long v2[2];
            v2[0] = *(const unsigned long long*)(Vs + k*68 + c0);
            v2[1] = *(const unsigned long long*)(Vs + k*68 + c0 + 2);
            #pragma unroll
            for (int i=0;i<8;i++){
                unsigned long long pd; DUP2(pd, pv[i]);
                FMA2(oacc[i][0], pd, v2[0], oacc[i][0]);
                FMA2(oacc[i][1], pd, v2[1], oacc[i][1]);
            }
        }
    }

    #pragma unroll
    for (int i=0;i<8;i++){
        float inv = 1.0f / l[i];
        float o0,o1,o2,o3;
        UNP2(o0,o1, oacc[i][0]);
        UNP2(o2,o3, oacc[i][1]);
        o0*=inv; o1*=inv; o2*=inv; o3*=inv;
        long long ixb = (tbase + r0 + i)*ND + hh*64 + c0;
        __nv_bfloat16 hb,lb;
        split_bf(o0,hb,lb); oh[ixb+0]=hb; ol[ixb+0]=lb;
        split_bf(o1,hb,lb); oh[ixb+1]=hb; ol[ixb+1]=lb;
        split_bf(o2,hb,lb); oh[ixb+2]=hb; ol[ixb+2]=lb;
        split_bf(o3,hb,lb); oh[ixb+3]=hb; ol[ixb+3]=lb;
    }
}

// ================= mma.sync bf16-split GEMM (R6 double-buffer core, z-batched) =====
#define TG_SMEM (2*4*128*40*2)

__global__ void __launch_bounds__(256,1) tgemm_kernel(
    const __nv_bfloat16* __restrict__ Ah, const __nv_bfloat16* __restrict__ Al, int lda, long long zA,
    const __nv_bfloat16* __restrict__ Bh, const __nv_bfloat16* __restrict__ Bl, int ldb, long long zB,
    float* __restrict__ C, int ldc,
    __nv_bfloat16* __restrict__ Oh, __nv_bfloat16* __restrict__ Ol, int ldo, long long zC,
    int M, int N, int K,
    const float* __restrict__ bias, int zbias, int act, int accum,
    const int* __restrict__ gidx, const int* __restrict__ gcount, int zg, int gatherA)
{
    extern __shared__ __nv_bfloat16 sm[];
    int z = blockIdx.z;
    Ah += z*zA; Al += z*zA;
    Bh += z*zB; Bl += z*zB;
    if (C){ C += z*zC; }
    if (Oh){ Oh += z*zC; Ol += z*zC; }
    if (bias) bias += (long long)z*zbias;
    if (gidx && zg){ gidx += (long long)z*zg; gcount += z; }

    int count = gcount ? *gcount : M;
    int m0 = blockIdx.y*128, n0 = blockIdx.x*128;
    if (count <= 0 || m0 >= count) return;

    int tid = threadIdx.x, wid = tid>>5, lane = tid&31;
    int wm = (wid>>2)*64, wn = (wid&3)*32;
    uint32_t smb = smem_u32(sm);

    float acc[4][4][4];
    #pragma unroll
    for (int mi=0;mi<4;mi++)
        #pragma unroll
        for (int ni=0;ni<4;ni++)
            #pragma unroll
            for (int f=0;f<4;f++) acc[mi][ni][f]=0.f;

    unsigned long long stA[2][4], stB[2][4];

    auto ldg_tile = [&](int kt){
        int kb = kt*32;
        #pragma unroll
        for (int u=0;u<4;u++){
            int c = tid + u*256;
            int row = c>>3, kc = (c&7)*4;
            int ar = m0+row; ar = ar<count ? ar : count-1;
            long long arow = gatherA ? gidx[ar] : ar;
            long long goff = arow*(long long)lda + kb + kc;
            stA[0][u] = *(const unsigned long long*)(Ah+goff);
            stA[1][u] = *(const unsigned long long*)(Al+goff);
            long long boff = (long long)(n0+row)*ldb + kb + kc;
            stB[0][u] = *(const unsigned long long*)(Bh+boff);
            stB[1][u] = *(const unsigned long long*)(Bl+boff);
        }
    };
    auto sts_tile = [&](int buf){
        __nv_bfloat16* base = sm + buf*20480;
        #pragma unroll
        for (int u=0;u<4;u++){
            int c = tid + u*256;
            int row = c>>3, kc = (c&7)*4;
            *(unsigned long long*)(base + row*40 + kc)         = stA[0][u];
            *(unsigned long long*)(base + 5120 + row*40 + kc)  = stA[1][u];
            *(unsigned long long*)(base + 10240 + row*40 + kc) = stB[0][u];
            *(unsigned long long*)(base + 15360 + row*40 + kc) = stB[1][u];
        }
    };

    ldg_tile(0);
    sts_tile(0);
    __syncthreads();

    int KT = K >> 5;
    int buf = 0;
    for (int kt=0; kt<KT; kt++){
        bool has_next = (kt+1) < KT;
        if (has_next) ldg_tile(kt+1);

        uint32_t bufb = smb + (uint32_t)buf*40960u;
        #pragma unroll
        for (int ks=0; ks<2; ks++){
            uint32_t ah[4][4], al[4][4];
            int arow_l = (lane&7) + ((lane>>3)&1)*8;
            int akcol  = ks*16 + (lane>>4)*8;
            #pragma unroll
            for (int mi=0;mi<4;mi++){
                uint32_t off = (uint32_t)((wm + mi*16 + arow_l)*80 + akcol*2);
                LDSM_X4(ah[mi][0],ah[mi][1],ah[mi][2],ah[mi][3], bufb + off);
                LDSM_X4(al[mi][0],al[mi][1],al[mi][2],al[mi][3], bufb + 10240u + off);
            }
            uint32_t bh[4][2], bl[4][2];
            int brow_l = lane&7;
            int bkcol  = ks*16 + ((lane>>3)&1)*8;
            #pragma unroll
            for (int ni=0;ni<4;ni++){
                uint32_t off = (uint32_t)((wn + ni*8 + brow_l)*80 + bkcol*2);
                LDSM_X2(bh[ni][0],bh[ni][1], bufb + 20480u + off);
                LDSM_X2(bl[ni][0],bl[ni][1], bufb + 30720u + off);
            }
            #pragma unroll
            for (int mi=0;mi<4;mi++)
                #pragma unroll
                for (int ni=0;ni<4;ni++){
                    MMA16816(acc[mi][ni], ah[mi], bh[ni]);
                    MMA16816(acc[mi][ni], ah[mi], bl[ni]);
                    MMA16816(acc[mi][ni], al[mi], bh[ni]);
                }
        }

        if (has_next){
            __syncthreads();
            sts_tile(buf^1);
            __syncthreads();
            buf ^= 1;
        }
    }

    // ---- epilogue (compact rows; no scatter) ----
    #pragma unroll
    for (int mi=0;mi<4;mi++){
        #pragma unroll
        for (int half=0; half<2; half++){
            int m = m0 + wm + mi*16 + (lane>>2) + half*8;
            if (m >= count) continue;
            #pragma unroll
            for (int ni=0;ni<4;ni++){
                int n = n0 + wn + ni*8 + (lane&3)*2;
                float v0 = acc[mi][ni][half*2+0];
                float v1 = acc[mi][ni][half*2+1];
                if (bias){ v0 += bias[n]; v1 += bias[n+1]; }
                if (act){ v0 = gelu_f(v0); v1 = gelu_f(v1); }
                if (C){
                    long long ix = (long long)m*ldc + n;
                    if (accum){ C[ix] += v0; C[ix+1] += v1; }
                    else      { C[ix]  = v0; C[ix+1]  = v1; }
                }
                if (Oh){
                    long long ix = (long long)m*ldo + n;
                    __nv_bfloat16 h0,l0,h1,l1;
                    split_bf(v0,h0,l0); split_bf(v1,h1,l1);
                    Oh[ix]=h0; Ol[ix]=l0; Oh[ix+1]=h1; Ol[ix+1]=l1;
                }
            }
        }
    }
}

struct TArg {
    const __nv_bfloat16 *Ah,*Al; int lda; long long zA;
    const __nv_bfloat16 *Bh,*Bl; int ldb; long long zB;
    float* C; int ldc;
    __nv_bfloat16 *Oh,*Ol; int ldo; long long zC;
    int M,N,K,batch;
    const float* bias; int zbias; int act; int accum;
    const int* gidx; const int* gcnt; int zg; int gA;
};
static void launch_t(const TArg& a){
    dim3 grid((unsigned)(a.N/128), (unsigned)((a.M+127)/128), (unsigned)a.batch);
    tgemm_kernel<<<grid,256,TG_SMEM>>>(a.Ah,a.Al,a.lda,a.zA, a.Bh,a.Bl,a.ldb,a.zB,
        a.C,a.ldc, a.Oh,a.Ol,a.ldo,a.zC, a.M,a.N,a.K,
        a.bias,a.zbias,a.act,a.accum, a.gidx,a.gcnt,a.zg,a.gA);
}

extern "C" void kernel_launch(void* const* d_in, const int* in_sizes, int n_in,
                              void* d_out, int out_size)
{
    (void)in_sizes; (void)n_in; (void)out_size;
    const int*   text  = (const int*)  d_in[0];
    const float* embed = (const float*)d_in[1];
    const float* conv_w= (const float*)d_in[2];
    const float* conv_b= (const float*)d_in[3];
    const float* Wq    = (const float*)d_in[4];
    const float* bq    = (const float*)d_in[5];
    const float* Wk    = (const float*)d_in[6];
    const float* bk    = (const float*)d_in[7];
    const float* Wv    = (const float*)d_in[8];
    const float* bv    = (const float*)d_in[9];
    const float* Wo    = (const float*)d_in[10];
    const float* bo    = (const float*)d_in[11];
    const float* rw    = (const float*)d_in[12];
    const float* rb    = (const float*)d_in[13];
    const float* ew1   = (const float*)d_in[14];
    const float* eb1   = (const float*)d_in[15];
    const float* ew2   = (const float*)d_in[16];
    const float* eb2   = (const float*)d_in[17];
    const float* ln1g  = (const float*)d_in[18];
    const float* ln1b  = (const float*)d_in[19];
    const float* ln2g  = (const float*)d_in[20];
    const float* ln2b  = (const float*)d_in[21];
    const float* lnfg  = (const float*)d_in[22];
    const float* lnfb  = (const float*)d_in[23];
    const float* outw  = (const float*)d_in[24];
    const float* outb  = (const float*)d_in[25];
    float* out = (float*)d_out;

    cudaFuncSetAttribute(tgemm_kernel, cudaFuncAttributeMaxDynamicSharedMemorySize, TG_SMEM);
    cudaFuncSetAttribute(flash_kernel, cudaFuncAttributeMaxDynamicSharedMemorySize, FL_SMEM);

    float *x,*h,*qkv,*h2,*bqkv;
    int *eidx,*ecnt;
    cudaGetSymbolAddress((void**)&x,  g_x);
    cudaGetSymbolAddress((void**)&h,  g_h);
    cudaGetSymbolAddress((void**)&qkv, g_qkv);
    cudaGetSymbolAddress((void**)&h2, g_h2);
    cudaGetSymbolAddress((void**)&bqkv, g_bqkv);
    cudaGetSymbolAddress((void**)&eidx, g_eidx);
    cudaGetSymbolAddress((void**)&ecnt, g_ecnt);

    __nv_bfloat16 *hbh,*hbl,*obh,*obl,*xch,*xcl,*h1h,*h1l;
    __nv_bfloat16 *wch,*wcl,*wqkvh,*wqkvl,*woh,*wol,*w1h,*w1l,*w2h,*w2l,*wouth,*woutl;
    cudaGetSymbolAddress((void**)&hbh, g_hb_h);  cudaGetSymbolAddress((void**)&hbl, g_hb_l);
    cudaGetSymbolAddress((void**)&obh, g_ob_h);  cudaGetSymbolAddress((void**)&obl, g_ob_l);
    cudaGetSymbolAddress((void**)&xch, g_xcb_h); cudaGetSymbolAddress((void**)&xcl, g_xcb_l);
    cudaGetSymbolAddress((void**)&h1h, g_h1b_h); cudaGetSymbolAddress((void**)&h1l, g_h1b_l);
    cudaGetSymbolAddress((void**)&wch, g_wcT_h); cudaGetSymbolAddress((void**)&wcl, g_wcT_l);
    cudaGetSymbolAddress((void**)&wqkvh, g_wqkvT_h); cudaGetSymbolAddress((void**)&wqkvl, g_wqkvT_l);
    cudaGetSymbolAddress((void**)&woh, g_woT_h); cudaGetSymbolAddress((void**)&wol, g_woT_l);
    cudaGetSymbolAddress((void**)&w1h, g_w1T_h); cudaGetSymbolAddress((void**)&w1l, g_w1T_l);
    cudaGetSymbolAddress((void**)&w2h, g_w2T_h); cudaGetSymbolAddress((void**)&w2l, g_w2T_l);
    cudaGetSymbolAddress((void**)&wouth, g_woutT_h); cudaGetSymbolAddress((void**)&woutl, g_woutT_l);

    const long long LQKV = (long long)NQKV*ND;
    const long long LDD  = (long long)ND*ND;

    // ---- weight repack/split (vectorized transpose: grid (N/32, K/64, z)) ----
    convw_kernel<<<(ND*3*ND+255)/256,256>>>(conv_w);
    wtrans_kernel<<<dim3(ND/32,ND/64,NL),256>>>(Wq, wqkvh,                 wqkvl,                 ND, ND, LQKV);
    wtrans_kernel<<<dim3(ND/32,ND/64,NL),256>>>(Wk, wqkvh+(size_t)ND*ND,   wqkvl+(size_t)ND*ND,   ND, ND, LQKV);
    wtrans_kernel<<<dim3(ND/32,ND/64,NL),256>>>(Wv, wqkvh+(size_t)2*ND*ND, wqkvl+(size_t)2*ND*ND, ND, ND, LQKV);
    wtrans_kernel<<<dim3(ND/32,ND/64,NL),256>>>(Wo, woh, wol, ND, ND, LDD);
    wtrans_kernel<<<dim3(NF/32,ND/64,NL*NE),256>>>(ew1, w1h, w1l, ND, NF, (long long)ND*NF);
    wtrans_kernel<<<dim3(ND/32,NF/64,NL*NE),256>>>(ew2, w2h, w2l, NF, ND, (long long)NF*ND);
    wtrans_kernel<<<dim3(NV/32,ND/64,1),256>>>(outw, wouth, woutl, ND, NV, (long long)ND*NV);
    bpack_kernel<<<(NL*NQKV+255)/256,256>>>(bq, bk, bv);

    // ---- tokenizer ----
    embed_kernel<<<NT,256>>>(text, embed);
    xcat_kernel<<<NT,256>>>();
    {   TArg a = {xch,xcl,3*ND,0, wch,wcl,3*ND,0, x,ND, nullptr,nullptr,0,0,
                  NT,ND,3*ND,1, conv_b,0,1, 1, nullptr,nullptr,0,0};
        launch_t(a); }

    for (int i=0;i<NL;i++){
        // ---- attention ----
        ln_kernel<<<NT,256>>>(x, ln1g+(size_t)i*ND, ln1b+(size_t)i*ND, h, hbh, hbl);
        {   TArg a = {hbh,hbl,ND,0, wqkvh+(size_t)i*LQKV, wqkvl+(size_t)i*LQKV, ND,0, qkv,NQKV,
                      nullptr,nullptr,0,0, NT,NQKV,ND,1, bqkv+(size_t)i*NQKV,0,0, 0, nullptr,nullptr,0,0};
            launch_t(a); }
        flash_kernel<<<dim3(NS/128, NB*NH),256,FL_SMEM>>>(qkv, obh, obl);
        {   TArg a = {obh,obl,ND,0, woh+(size_t)i*LDD, wol+(size_t)i*LDD, ND,0, x,ND,
                      nullptr,nullptr,0,0, NT,ND,ND,1, bo+(size_t)i*ND,0,0, 1, nullptr,nullptr,0,0};
            launch_t(a); }

        // ---- MoE (top-2, batched over experts via grid.z) ----
        ln_kernel<<<NT,256>>>(x, ln2g+(size_t)i*ND, ln2b+(size_t)i*ND, h, hbh, hbl);
        zero_cnt_kernel<<<1,32>>>();
        router_kernel<<<NT/4, dim3(32,4)>>>(h, rw+(size_t)i*ND*NE, rb+(size_t)i*NE);
        {   TArg a = {hbh,hbl,ND,0,
                      w1h+(size_t)i*NE*NF*ND, w1l+(size_t)i*NE*NF*ND, ND,(long long)NF*ND,
                      nullptr,0,
                      h1h,h1l,NF,(long long)NT*NF,
                      NT,NF,ND,NE,
                      eb1+(size_t)i*NE*NF, NF, 1, 0,
                      eidx, ecnt, NT, 1};
            launch_t(a); }
        {   TArg a = {h1h,h1l,NF,(long long)NT*NF,
                      w2h+(size_t)i*NE*ND*NF, w2l+(size_t)i*NE*ND*NF, NF,(long long)ND*NF,
                      h2,ND,
                      nullptr,nullptr,0,(long long)NT*ND,
                      NT,ND,NF,NE,
                      eb2+(size_t)i*NE*ND, ND, 0, 0,
                      eidx, ecnt, NT, 0};
            launch_t(a); }
        moe_combine_kernel<<<NT,192>>>();
    }

    // ---- final LN + output projection ----
    ln_kernel<<<NT,256>>>(x, lnfg, lnfb, h, hbh, hbl);
    {   TArg a = {hbh,hbl,ND,0, wouth,woutl,ND,0, out,NV, nullptr,nullptr,0,0,
                  NT,NV,ND,1, outb,0,0, 0, nullptr,nullptr,0,0};
        launch_t(a); }
}

// round 14
// speedup vs baseline: 1.0365x; 1.0011x over previous
#include <cuda_runtime.h>
#include <cuda_bf16.h>
#include <math.h>
#include <stdint.h>

#define NL 4
#define NB 4
#define NS 1024
#define ND 768
#define NF 3072
#define NE 4
#define NV 256
#define NH 12
#define NDH 64
#define NT (NB*NS)
#define NQKV 2304

// ================= packed f32x2 helpers =================
#define FMA2(d,a,b,c) asm("fma.rn.f32x2 %0, %1, %2, %3;" : "=l"(d) : "l"(a), "l"(b), "l"(c))
#define MUL2(d,a,b)   asm("mul.rn.f32x2 %0, %1, %2;" : "=l"(d) : "l"(a), "l"(b))
#define DUP2(d,s)     asm("mov.b64 %0, {%1, %1};" : "=l"(d) : "f"(s))
#define UNP2(lo,hi,v) asm("mov.b64 {%0, %1}, %2;" : "=f"(lo), "=f"(hi) : "l"(v))

__device__ __forceinline__ uint32_t smem_u32(const void* p){
    uint32_t a;
    asm("{ .reg .u64 t; cvta.to.shared.u64 t, %1; cvt.u32.u64 %0, t; }" : "=r"(a) : "l"(p));
    return a;
}

// ldmatrix / mma wrappers (sm_80+, OK on compute_103)
#define LDSM_X4(r0,r1,r2,r3,addr) \
    asm volatile("ldmatrix.sync.aligned.m8n8.x4.shared.b16 {%0,%1,%2,%3}, [%4];" \
        : "=r"(r0),"=r"(r1),"=r"(r2),"=r"(r3) : "r"(addr))
#define LDSM_X2(r0,r1,addr) \
    asm volatile("ldmatrix.sync.aligned.m8n8.x2.shared.b16 {%0,%1}, [%2];" \
        : "=r"(r0),"=r"(r1) : "r"(addr))
#define MMA16816(d,a,b) \
    asm volatile("mma.sync.aligned.m16n8k16.row.col.f32.bf16.bf16.f32 " \
        "{%0,%1,%2,%3}, {%4,%5,%6,%7}, {%8,%9}, {%0,%1,%2,%3};" \
        : "+f"((d)[0]),"+f"((d)[1]),"+f"((d)[2]),"+f"((d)[3]) \
        : "r"((a)[0]),"r"((a)[1]),"r"((a)[2]),"r"((a)[3]), "r"((b)[0]),"r"((b)[1]))

// ================= scratch =================
__device__ float g_x[NT*ND];
__device__ float g_h[NT*ND];
__device__ float g_qkv[(size_t)NT*NQKV];
__device__ float g_h2[(size_t)NE*NT*ND];      // compact per-expert MoE outputs
__device__ float g_bqkv[NL*NQKV];
__device__ float g_sgate[NT*2];               // top-2 gates per token
__device__ int   g_slot[NT*2];                // e*NT+pos per token
__device__ int   g_eidx[NE*NT];
__device__ int   g_ecnt[NE];

__device__ __nv_bfloat16 g_hb_h[NT*ND],  g_hb_l[NT*ND];
__device__ __nv_bfloat16 g_ob_h[NT*ND],  g_ob_l[NT*ND];
__device__ __nv_bfloat16 g_xcb_h[NT*3*ND], g_xcb_l[NT*3*ND];
__device__ __nv_bfloat16 g_h1b_h[(size_t)NE*NT*NF], g_h1b_l[(size_t)NE*NT*NF];
__device__ __nv_bfloat16 g_wcT_h[ND*3*ND], g_wcT_l[ND*3*ND];
__device__ __nv_bfloat16 g_wqkvT_h[NL*NQKV*ND], g_wqkvT_l[NL*NQKV*ND];
__device__ __nv_bfloat16 g_woT_h[NL*ND*ND], g_woT_l[NL*ND*ND];
__device__ __nv_bfloat16 g_w1T_h[NL*NE*NF*ND], g_w1T_l[NL*NE*NF*ND];
__device__ __nv_bfloat16 g_w2T_h[NL*NE*ND*NF], g_w2T_l[NL*NE*ND*NF];
__device__ __nv_bfloat16 g_woutT_h[NV*ND], g_woutT_l[NV*ND];

__device__ __forceinline__ float gelu_f(float x){
    const float c = 0.7978845608028654f;
    return 0.5f*x*(1.0f + tanhf(c*(x + 0.044715f*x*x*x)));
}
__device__ __forceinline__ void split_bf(float v, __nv_bfloat16& h, __nv_bfloat16& l){
    h = __float2bfloat16(v);
    l = __float2bfloat16(v - __bfloat162float(h));
}

// ================= small kernels =================
__global__ void embed_kernel(const int* __restrict__ text, const float* __restrict__ emb){
    int t = blockIdx.x;
    int tok = text[t];
    const float* src = emb + (size_t)tok*ND;
    float* dst = g_x + (size_t)t*ND;
    for (int d = threadIdx.x; d < ND; d += blockDim.x) dst[d] = src[d];
}

__global__ void convw_kernel(const float* __restrict__ w){
    int idx = blockIdx.x*blockDim.x + threadIdx.x;
    if (idx >= ND*3*ND) return;
    int o = idx / (3*ND);
    int r = idx % (3*ND);
    int k = r / ND, i = r % ND;
    float v = w[((size_t)o*ND + i)*3 + k];
    split_bf(v, g_wcT_h[idx], g_wcT_l[idx]);
}

// vectorized transpose+split: in [K][N] (z-stride K*N) -> out [N][K] (z-stride ozs)
// tiles: 64 (K) x 32 (N); packed bf16x2 cvt; 16B stores. Requires K%64==0, N%32==0.
__global__ void wtrans_kernel(const float* __restrict__ in, __nv_bfloat16* __restrict__ hi,
                              __nv_bfloat16* __restrict__ lo, int K, int N, long long ozs){
    __shared__ float t[64][33];
    size_t zi = (size_t)blockIdx.z*K*N;
    size_t zo = (size_t)blockIdx.z*ozs;
    int n0 = blockIdx.x*32, k0 = blockIdx.y*64;
    int tid = threadIdx.x;   // 256
    #pragma unroll
    for (int u=0;u<2;u++){
        int c = tid + u*256;         // 0..511
        int kr = c >> 3;             // 0..63
        int nc = (c & 7) * 4;        // 0..28
        float4 v = *(const float4*)(in + zi + (size_t)(k0+kr)*N + n0 + nc);
        t[kr][nc+0]=v.x; t[kr][nc+1]=v.y; t[kr][nc+2]=v.z; t[kr][nc+3]=v.w;
    }
    __syncthreads();
    int nr = tid >> 3;               // 0..31
    int kc = (tid & 7) * 8;          // 0..56
    float v[8];
    #pragma unroll
    for (int j=0;j<8;j++) v[j] = t[kc+j][nr];
    uint32_t hp[4], lp[4];
    #pragma unroll
    for (int j=0;j<4;j++){
        uint32_t ph;
        asm("cvt.rn.bf16x2.f32 %0, %1, %2;" : "=r"(ph) : "f"(v[2*j+1]), "f"(v[2*j]));
        hp[j] = ph;
        float h0 = __uint_as_float(ph << 16);
        float h1 = __uint_as_float(ph & 0xffff0000u);
        float l0 = v[2*j]   - h0;
        float l1 = v[2*j+1] - h1;
        uint32_t pl;
        asm("cvt.rn.bf16x2.f32 %0, %1, %2;" : "=r"(pl) : "f"(l1), "f"(l0));
        lp[j] = pl;
    }
    size_t oo = zo + (size_t)(n0+nr)*K + k0 + kc;   // element offset; *2 bytes, 16B aligned
    *(uint4*)((char*)hi + oo*2) = *(const uint4*)hp;
    *(uint4*)((char*)lo + oo*2) = *(const uint4*)lp;
}

__global__ void bpack_kernel(const float* __restrict__ bq, const float* __restrict__ bk,
                             const float* __restrict__ bv){
    int idx = blockIdx.x*blockDim.x + threadIdx.x;
    if (idx >= NL*NQKV) return;
    int layer = idx / NQKV, c = idx % NQKV;
    float v;
    if (c < ND)            v = bq[layer*ND + c];
    else if (c < 2*ND)     v = bk[layer*ND + c - ND];
    else                   v = bv[layer*ND + c - 2*ND];
    g_bqkv[idx] = v;
}

__global__ void xcat_kernel(){
    int t = blockIdx.x;
    int s = t % NS;
    size_t base = (size_t)t*3*ND;
    for (int idx = threadIdx.x; idx < 3*ND; idx += blockDim.x) {
        int k = idx / ND, i = idx % ND;
        int sp = s + k - 1;
        float val = (sp >= 0 && sp < NS) ? g_x[(size_t)(t + k - 1)*ND + i] : 0.0f;
        __nv_bfloat16 h,l; split_bf(val,h,l);
        g_xcb_h[base+idx]=h; g_xcb_l[base+idx]=l;
    }
}

__global__ void ln_kernel(const float* __restrict__ x, const float* __restrict__ g,
                          const float* __restrict__ b, float* __restrict__ out,
                          __nv_bfloat16* __restrict__ oh, __nv_bfloat16* __restrict__ ol){
    __shared__ float red[256];
    int r = blockIdx.x;
    const float* xr = x + (size_t)r*ND;
    int tid = threadIdx.x;
    float s = 0.f;
    for (int d = tid; d < ND; d += 256) s += xr[d];
    red[tid] = s; __syncthreads();
    for (int o = 128; o > 0; o >>= 1){ if (tid < o) red[tid] += red[tid+o]; __syncthreads(); }
    float mean = red[0] / (float)ND;
    __syncthreads();
    float vs = 0.f;
    for (int d = tid; d < ND; d += 256){ float dd = xr[d]-mean; vs += dd*dd; }
    red[tid] = vs; __syncthreads();
    for (int o = 128; o > 0; o >>= 1){ if (tid < o) red[tid] += red[tid+o]; __syncthreads(); }
    float rstd = rsqrtf(red[0]/(float)ND + 1e-5f);
    size_t base = (size_t)r*ND;
    for (int d = tid; d < ND; d += 256){
        float v = (xr[d]-mean)*rstd*g[d] + b[d];
        out[base+d] = v;
        __nv_bfloat16 h,l; split_bf(v,h,l);
        oh[base+d]=h; ol[base+d]=l;
    }
}

__global__ void zero_cnt_kernel(){
    if (threadIdx.x < NE) g_ecnt[threadIdx.x] = 0;
}

// router: softmax -> top2 -> compact lists + (slot, gate) records
__global__ void router_kernel(const float* __restrict__ h, const float* __restrict__ rw,
                              const float* __restrict__ rb){
    int t = blockIdx.x*blockDim.y + threadIdx.y;
    int lane = threadIdx.x;
    float a0=0.f,a1=0.f,a2=0.f,a3=0.f;
    const float* hr = h + (size_t)t*ND;
    for (int d = lane; d < ND; d += 32){
        float hv = hr[d];
        a0 += hv*rw[d*NE+0];
        a1 += hv*rw[d*NE+1];
        a2 += hv*rw[d*NE+2];
        a3 += hv*rw[d*NE+3];
    }
    #pragma unroll
    for (int o=16;o>0;o>>=1){
        a0 += __shfl_down_sync(0xffffffffu, a0, o);
        a1 += __shfl_down_sync(0xffffffffu, a1, o);
        a2 += __shfl_down_sync(0xffffffffu, a2, o);
        a3 += __shfl_down_sync(0xffffffffu, a3, o);
    }
    if (lane==0){
        float l[4]={a0+rb[0],a1+rb[1],a2+rb[2],a3+rb[3]};
        float lm = fmaxf(fmaxf(l[0],l[1]),fmaxf(l[2],l[3]));
        float p[4]; float sum=0.f;
        #pragma unroll
        for(int e=0;e<4;e++){ p[e]=expf(l[e]-lm); sum+=p[e]; }
        #pragma unroll
        for(int e=0;e<4;e++) p[e]/=sum;
        int i0=0;
        #pragma unroll
        for(int e=1;e<4;e++) if(p[e]>p[i0]) i0=e;
        int i1=-1;
        #pragma unroll
        for(int e=0;e<4;e++){ if(e==i0) continue; if(i1<0 || p[e]>p[i1]) i1=e; }
        float gs = p[i0]+p[i1];
        int pos0 = atomicAdd(&g_ecnt[i0], 1); g_eidx[i0*NT+pos0]=t;
        int pos1 = atomicAdd(&g_ecnt[i1], 1); g_eidx[i1*NT+pos1]=t;
        g_slot[2*t+0]  = i0*NT+pos0;
        g_slot[2*t+1]  = i1*NT+pos1;
        g_sgate[2*t+0] = p[i0]/gs;
        g_sgate[2*t+1] = p[i1]/gs;
    }
}

// combine: x[t] += g0*h2[slot0] + g1*h2[slot1]
__global__ void moe_combine_kernel(){
    int t = blockIdx.x;
    long long s0 = g_slot[2*t+0], s1 = g_slot[2*t+1];
    float w0 = g_sgate[2*t+0], w1 = g_sgate[2*t+1];
    const float4* a = (const float4*)(g_h2 + s0*ND);
    const float4* b = (const float4*)(g_h2 + s1*ND);
    float4* xp = (float4*)(g_x + (size_t)t*ND);
    int d = threadIdx.x;
    float4 xv = xp[d], av = a[d], bv = b[d];
    xv.x += w0*av.x + w1*bv.x;
    xv.y += w0*av.y + w1*bv.y;
    xv.z += w0*av.z + w1*bv.z;
    xv.w += w0*av.w + w1*bv.w;
    xp[d] = xv;
}

// ================= fused flash attention (fp32 f32x2), 2 CTAs/SM =================
#define FL_SMEM (25600*4)
__global__ void __launch_bounds__(256,2) flash_kernel(const float* __restrict__ qkv,
        __nv_bfloat16* __restrict__ oh, __nv_bfloat16* __restrict__ ol){
    extern __shared__ float fs[];
    float* Qs = fs;
    float* Ks = fs + 8448;
    float* Vs = fs + 12800;
    float* Ps = fs + 17152;

    int qb = blockIdx.x;
    int bh = blockIdx.y;
    int b = bh / NH, hh = bh - b*NH;
    int tid = threadIdx.x;
    int tx = tid & 15, ty = tid >> 4;
    int r0 = ty*8, c0 = tx*4;
    long long tbase = (long long)b*NS + qb*128;
    int qcol = hh*64, kcol = ND + hh*64, vcol = 2*ND + hh*64;

    for (int idx = tid; idx < 128*16; idx += 256){
        int row = idx >> 4, ds = (idx & 15)*4;
        float4 qv = *(const float4*)(qkv + (tbase+row)*NQKV + qcol + ds);
        Qs[(ds+0)*132+row] = qv.x*0.125f;
        Qs[(ds+1)*132+row] = qv.y*0.125f;
        Qs[(ds+2)*132+row] = qv.z*0.125f;
        Qs[(ds+3)*132+row] = qv.w*0.125f;
    }

    float m[8], l[8];
    unsigned long long oacc[8][2];
    #pragma unroll
    for (int i=0;i<8;i++){ m[i]=-1e30f; l[i]=0.f; oacc[i][0]=0ULL; oacc[i][1]=0ULL; }

    long long kvbase = (long long)b*NS;
    for (int kt=0; kt<16; kt++){
        __syncthreads();
        for (int idx = tid; idx < 64*16; idx += 256){
            int krow = idx >> 4, ds = (idx & 15)*4;
            long long grow = (kvbase + kt*64 + krow)*NQKV;
            float4 kv = *(const float4*)(qkv + grow + kcol + ds);
            Ks[(ds+0)*68+krow] = kv.x;
            Ks[(ds+1)*68+krow] = kv.y;
            Ks[(ds+2)*68+krow] = kv.z;
            Ks[(ds+3)*68+krow] = kv.w;
            float4 vv = *(const float4*)(qkv + grow + vcol + ds);
            *(float4*)(Vs + krow*68 + ds) = vv;
        }
        __syncthreads();

        unsigned long long sa[8][2];
        #pragma unroll
        for (int i=0;i<8;i++){ sa[i][0]=0ULL; sa[i][1]=0ULL; }
        #pragma unroll 4
        for (int d=0; d<64; d++){
            float av[8];
            *(float4*)&av[0] = *(const float4*)(Qs + d*132 + r0);
            *(float4*)&av[4] = *(const float4*)(Qs + d*132 + r0 + 4);
            unsigned long long k2[2];
            k2[0] = *(const unsigned long long*)(Ks + d*68 + c0);
            k2[1] = *(const unsigned long long*)(Ks + d*68 + c0 + 2);
            #pragma unroll
            for (int i=0;i<8;i++){
                unsigned long long ad; DUP2(ad, av[i]);
                FMA2(sa[i][0], ad, k2[0], sa[i][0]);
                FMA2(sa[i][1], ad, k2[1], sa[i][1]);
            }
        }

        #pragma unroll
        for (int i=0;i<8;i++){
            float s0,s1,s2,s3;
            UNP2(s0,s1, sa[i][0]);
            UNP2(s2,s3, sa[i][1]);
            float lm = fmaxf(fmaxf(s0,s1), fmaxf(s2,s3));
            #pragma unroll
            for (int ms=8; ms>0; ms>>=1)
                lm = fmaxf(lm, __shfl_xor_sync(0xffffffffu, lm, ms));
            float mnew = fmaxf(m[i], lm);
            float sc = expf(m[i]-mnew);
            float p0 = expf(s0-mnew), p1 = expf(s1-mnew);
            float p2 = expf(s2-mnew), p3 = expf(s3-mnew);
            float rs = (p0+p1)+(p2+p3);
            #pragma unroll
            for (int ms=8; ms>0; ms>>=1)
                rs += __shfl_xor_sync(0xffffffffu, rs, ms);
            l[i] = l[i]*sc + rs;
            m[i] = mnew;
            unsigned long long scd; DUP2(scd, sc);
            MUL2(oacc[i][0], oacc[i][0], scd);
            MUL2(oacc[i][1], oacc[i][1], scd);
            Ps[(c0+0)*132 + r0+i] = p0;
            Ps[(c0+1)*132 + r0+i] = p1;
            Ps[(c0+2)*132 + r0+i] = p2;
            Ps[(c0+3)*132 + r0+i] = p3;
        }
        __syncthreads();

        #pragma unroll 4
        for (int k=0; k<64; k++){
            float pv[8];
            *(float4*)&pv[0] = *(const float4*)(Ps + k*132 + r0);
            *(float4*)&pv[4] = *(const float4*)(Ps + k*132 + r0 + 4);
            unsigned long long v2[2];
            v2[0] = *(const unsigned long long*)(Vs + k*68 + c0);
            v2[1] = *(const unsigned long long*)(Vs + k*68 + c0 + 2);
            #pragma unroll
            for (int i=0;i<8;i++){
                unsigned long long pd; DUP2(pd, pv[i]);
                FMA2(oacc[i][0], pd, v2[0], oacc[i][0]);
                FMA2(oacc[i][1], pd, v2[1], oacc[i][1]);
            }
        }
    }

    #pragma unroll
    for (int i=0;i<8;i++){
        float inv = 1.0f / l[i];
        float o0,o1,o2,o3;
        UNP2(o0,o1, oacc[i][0]);
        UNP2(o2,o3, oacc[i][1]);
        o0*=inv; o1*=inv; o2*=inv; o3*=inv;
        long long ixb = (tbase + r0 + i)*ND + hh*64 + c0;
        __nv_bfloat16 hb,lb;
        split_bf(o0,hb,lb); oh[ixb+0]=hb; ol[ixb+0]=lb;
        split_bf(o1,hb,lb); oh[ixb+1]=hb; ol[ixb+1]=lb;
        split_bf(o2,hb,lb); oh[ixb+2]=hb; ol[ixb+2]=lb;
        split_bf(o3,hb,lb); oh[ixb+3]=hb; ol[ixb+3]=lb;
    }
}

// ================= mma.sync bf16-split GEMM (R6 double-buffer core, z-batched) =====
#define TG_SMEM (2*4*128*40*2)

__global__ void __launch_bounds__(256,1) tgemm_kernel(
    const __nv_bfloat16* __restrict__ Ah, const __nv_bfloat16* __restrict__ Al, int lda, long long zA,
    const __nv_bfloat16* __restrict__ Bh, const __nv_bfloat16* __restrict__ Bl, int ldb, long long zB,
    float* __restrict__ C, int ldc,
    __nv_bfloat16* __restrict__ Oh, __nv_bfloat16* __restrict__ Ol, int ldo, long long zC,
    int M, int N, int K,
    const float* __restrict__ bias, int zbias, int act, int accum,
    const int* __restrict__ gidx, const int* __restrict__ gcount, int zg, int gatherA)
{
    extern __shared__ __nv_bfloat16 sm[];
    int z = blockIdx.z;
    Ah += z*zA; Al += z*zA;
    Bh += z*zB; Bl += z*zB;
    if (C){ C += z*zC; }
    if (Oh){ Oh += z*zC; Ol += z*zC; }
    if (bias) bias += (long long)z*zbias;
    if (gidx && zg){ gidx += (long long)z*zg; gcount += z; }

    int count = gcount ? *gcount : M;
    int m0 = blockIdx.y*128, n0 = blockIdx.x*128;
    if (count <= 0 || m0 >= count) return;

    int tid = threadIdx.x, wid = tid>>5, lane = tid&31;
    int wm = (wid>>2)*64, wn = (wid&3)*32;
    uint32_t smb = smem_u32(sm);

    float acc[4][4][4];
    #pragma unroll
    for (int mi=0;mi<4;mi++)
        #pragma unroll
        for (int ni=0;ni<4;ni++)
            #pragma unroll
            for (int f=0;f<4;f++) acc[mi][ni][f]=0.f;

    unsigned long long stA[2][4], stB[2][4];

    auto ldg_tile = [&](int kt){
        int kb = kt*32;
        #pragma unroll
        for (int u=0;u<4;u++){
            int c = tid + u*256;
            int row = c>>3, kc = (c&7)*4;
            int ar = m0+row; ar = ar<count ? ar : count-1;
            long long arow = gatherA ? gidx[ar] : ar;
            long long goff = arow*(long long)lda + kb + kc;
            stA[0][u] = *(const unsigned long long*)(Ah+goff);
            stA[1][u] = *(const unsigned long long*)(Al+goff);
            long long boff = (long long)(n0+row)*ldb + kb + kc;
            stB[0][u] = *(const unsigned long long*)(Bh+boff);
            stB[1][u] = *(const unsigned long long*)(Bl+boff);
        }
    };
    auto sts_tile = [&](int buf){
        __nv_bfloat16* base = sm + buf*20480;
        #pragma unroll
        for (int u=0;u<4;u++){
            int c = tid + u*256;
            int row = c>>3, kc = (c&7)*4;
            *(unsigned long long*)(base + row*40 + kc)         = stA[0][u];
            *(unsigned long long*)(base + 5120 + row*40 + kc)  = stA[1][u];
            *(unsigned long long*)(base + 10240 + row*40 + kc) = stB[0][u];
            *(unsigned long long*)(base + 15360 + row*40 + kc) = stB[1][u];
        }
    };

    ldg_tile(0);
    sts_tile(0);
    __syncthreads();

    int KT = K >> 5;
    int buf = 0;
    for (int kt=0; kt<KT; kt++){
        bool has_next = (kt+1) < KT;
        if (has_next) ldg_tile(kt+1);

        uint32_t bufb = smb + (uint32_t)buf*40960u;
        #pragma unroll
        for (int ks=0; ks<2; ks++){
            uint32_t ah[4][4], al[4][4];
            int arow_l = (lane&7) + ((lane>>3)&1)*8;
            int akcol  = ks*16 + (lane>>4)*8;
            #pragma unroll
            for (int mi=0;mi<4;mi++){
                uint32_t off = (uint32_t)((wm + mi*16 + arow_l)*80 + akcol*2);
                LDSM_X4(ah[mi][0],ah[mi][1],ah[mi][2],ah[mi][3], bufb + off);
                LDSM_X4(al[mi][0],al[mi][1],al[mi][2],al[mi][3], bufb + 10240u + off);
            }
            uint32_t bh[4][2], bl[4][2];
            int brow_l = lane&7;
            int bkcol  = ks*16 + ((lane>>3)&1)*8;
            #pragma unroll
            for (int ni=0;ni<4;ni++){
                uint32_t off = (uint32_t)((wn + ni*8 + brow_l)*80 + bkcol*2);
                LDSM_X2(bh[ni][0],bh[ni][1], bufb + 20480u + off);
                LDSM_X2(bl[ni][0],bl[ni][1], bufb + 30720u + off);
            }
            #pragma unroll
            for (int mi=0;mi<4;mi++)
                #pragma unroll
                for (int ni=0;ni<4;ni++){
                    MMA16816(acc[mi][ni], ah[mi], bh[ni]);
                    MMA16816(acc[mi][ni], ah[mi], bl[ni]);
                    MMA16816(acc[mi][ni], al[mi], bh[ni]);
                }
        }

        if (has_next){
            __syncthreads();
            sts_tile(buf^1);
            __syncthreads();
            buf ^= 1;
        }
    }

    // ---- epilogue (compact rows; no scatter) ----
    #pragma unroll
    for (int mi=0;mi<4;mi++){
        #pragma unroll
        for (int half=0; half<2; half++){
            int m = m0 + wm + mi*16 + (lane>>2) + half*8;
            if (m >= count) continue;
            #pragma unroll
            for (int ni=0;ni<4;ni++){
                int n = n0 + wn + ni*8 + (lane&3)*2;
                float v0 = acc[mi][ni][half*2+0];
                float v1 = acc[mi][ni][half*2+1];
                if (bias){ v0 += bias[n]; v1 += bias[n+1]; }
                if (act){ v0 = gelu_f(v0); v1 = gelu_f(v1); }
                if (C){
                    long long ix = (long long)m*ldc + n;
                    if (accum){ C[ix] += v0; C[ix+1] += v1; }
                    else      { C[ix]  = v0; C[ix+1]  = v1; }
                }
                if (Oh){
                    long long ix = (long long)m*ldo + n;
                    __nv_bfloat16 h0,l0,h1,l1;
                    split_bf(v0,h0,l0); split_bf(v1,h1,l1);
                    Oh[ix]=h0; Ol[ix]=l0; Oh[ix+1]=h1; Ol[ix+1]=l1;
                }
            }
        }
    }
}

struct TArg {
    const __nv_bfloat16 *Ah,*Al; int lda; long long zA;
    const __nv_bfloat16 *Bh,*Bl; int ldb; long long zB;
    float* C; int ldc;
    __nv_bfloat16 *Oh,*Ol; int ldo; long long zC;
    int M,N,K,batch;
    const float* bias; int zbias; int act; int accum;
    const int* gidx; const int* gcnt; int zg; int gA;
};
static void launch_t(const TArg& a){
    dim3 grid((unsigned)(a.N/128), (unsigned)((a.M+127)/128), (unsigned)a.batch);
    tgemm_kernel<<<grid,256,TG_SMEM>>>(a.Ah,a.Al,a.lda,a.zA, a.Bh,a.Bl,a.ldb,a.zB,
        a.C,a.ldc, a.Oh,a.Ol,a.ldo,a.zC, a.M,a.N,a.K,
        a.bias,a.zbias,a.act,a.accum, a.gidx,a.gcnt,a.zg,a.gA);
}

extern "C" void kernel_launch(void* const* d_in, const int* in_sizes, int n_in,
                              void* d_out, int out_size)
{
    (void)in_sizes; (void)n_in; (void)out_size;
    const int*   text  = (const int*)  d_in[0];
    const float* embed = (const float*)d_in[1];
    const float* conv_w= (const float*)d_in[2];
    const float* conv_b= (const float*)d_in[3];
    const float* Wq    = (const float*)d_in[4];
    const float* bq    = (const float*)d_in[5];
    const float* Wk    = (const float*)d_in[6];
    const float* bk    = (const float*)d_in[7];
    const float* Wv    = (const float*)d_in[8];
    const float* bv    = (const float*)d_in[9];
    const float* Wo    = (const float*)d_in[10];
    const float* bo    = (const float*)d_in[11];
    const float* rw    = (const float*)d_in[12];
    const float* rb    = (const float*)d_in[13];
    const float* ew1   = (const float*)d_in[14];
    const float* eb1   = (const float*)d_in[15];
    const float* ew2   = (const float*)d_in[16];
    const float* eb2   = (const float*)d_in[17];
    const float* ln1g  = (const float*)d_in[18];
    const float* ln1b  = (const float*)d_in[19];
    const float* ln2g  = (const float*)d_in[20];
    const float* ln2b  = (const float*)d_in[21];
    const float* lnfg  = (const float*)d_in[22];
    const float* lnfb  = (const float*)d_in[23];
    const float* outw  = (const float*)d_in[24];
    const float* outb  = (const float*)d_in[25];
    float* out = (float*)d_out;

    cudaFuncSetAttribute(tgemm_kernel, cudaFuncAttributeMaxDynamicSharedMemorySize, TG_SMEM);
    cudaFuncSetAttribute(flash_kernel, cudaFuncAttributeMaxDynamicSharedMemorySize, FL_SMEM);

    float *x,*h,*qkv,*h2,*bqkv;
    int *eidx,*ecnt;
    cudaGetSymbolAddress((void**)&x,  g_x);
    cudaGetSymbolAddress((void**)&h,  g_h);
    cudaGetSymbolAddress((void**)&qkv, g_qkv);
    cudaGetSymbolAddress((void**)&h2, g_h2);
    cudaGetSymbolAddress((void**)&bqkv, g_bqkv);
    cudaGetSymbolAddress((void**)&eidx, g_eidx);
    cudaGetSymbolAddress((void**)&ecnt, g_ecnt);

    __nv_bfloat16 *hbh,*hbl,*obh,*obl,*xch,*xcl,*h1h,*h1l;
    __nv_bfloat16 *wch,*wcl,*wqkvh,*wqkvl,*woh,*wol,*w1h,*w1l,*w2h,*w2l,*wouth,*woutl;
    cudaGetSymbolAddress((void**)&hbh, g_hb_h);  cudaGetSymbolAddress((void**)&hbl, g_hb_l);
    cudaGetSymbolAddress((void**)&obh, g_ob_h);  cudaGetSymbolAddress((void**)&obl, g_ob_l);
    cudaGetSymbolAddress((void**)&xch, g_xcb_h); cudaGetSymbolAddress((void**)&xcl, g_xcb_l);
    cudaGetSymbolAddress((void**)&h1h, g_h1b_h); cudaGetSymbolAddress((void**)&h1l, g_h1b_l);
    cudaGetSymbolAddress((void**)&wch, g_wcT_h); cudaGetSymbolAddress((void**)&wcl, g_wcT_l);
    cudaGetSymbolAddress((void**)&wqkvh, g_wqkvT_h); cudaGetSymbolAddress((void**)&wqkvl, g_wqkvT_l);
    cudaGetSymbolAddress((void**)&woh, g_woT_h); cudaGetSymbolAddress((void**)&wol, g_woT_l);
    cudaGetSymbolAddress((void**)&w1h, g_w1T_h); cudaGetSymbolAddress((void**)&w1l, g_w1T_l);
    cudaGetSymbolAddress((void**)&w2h, g_w2T_h); cudaGetSymbolAddress((void**)&w2l, g_w2T_l);
    cudaGetSymbolAddress((void**)&wouth, g_woutT_h); cudaGetSymbolAddress((void**)&woutl, g_woutT_l);

    const long long LQKV = (long long)NQKV*ND;
    const long long LDD  = (long long)ND*ND;

    // ---- weight repack/split (vectorized transpose: grid (N/32, K/64, z)) ----
    convw_kernel<<<(ND*3*ND+255)/256,256>>>(conv_w);
    wtrans_kernel<<<dim3(ND/32,ND/64,NL),256>>>(Wq, wqkvh,                 wqkvl,                 ND, ND, LQKV);
    wtrans_kernel<<<dim3(ND/32,ND/64,NL),256>>>(Wk, wqkvh+(size_t)ND*ND,   wqkvl+(size_t)ND*ND,   ND, ND, LQKV);
    wtrans_kernel<<<dim3(ND/32,ND/64,NL),256>>>(Wv, wqkvh+(size_t)2*ND*ND, wqkvl+(size_t)2*ND*ND, ND, ND, LQKV);
    wtrans_kernel<<<dim3(ND/32,ND/64,NL),256>>>(Wo, woh, wol, ND, ND, LDD);
    wtrans_kernel<<<dim3(NF/32,ND/64,NL*NE),256>>>(ew1, w1h, w1l, ND, NF, (long long)ND*NF);
    wtrans_kernel<<<dim3(ND/32,NF/64,NL*NE),256>>>(ew2, w2h, w2l, NF, ND, (long long)NF*ND);
    wtrans_kernel<<<dim3(NV/32,ND/64,1),256>>>(outw, wouth, woutl, ND, NV, (long long)ND*NV);
    bpack_kernel<<<(NL*NQKV+255)/256,256>>>(bq, bk, bv);

    // ---- tokenizer ----
    embed_kernel<<<NT,256>>>(text, embed);
    xcat_kernel<<<NT,256>>>();
    {   TArg a = {xch,xcl,3*ND,0, wch,wcl,3*ND,0, x,ND, nullptr,nullptr,0,0,
                  NT,ND,3*ND,1, conv_b,0,1, 1, nullptr,nullptr,0,0};
        launch_t(a); }

    for (int i=0;i<NL;i++){
        // ---- attention ----
        ln_kernel<<<NT,256>>>(x, ln1g+(size_t)i*ND, ln1b+(size_t)i*ND, h, hbh, hbl);
        {   TArg a = {hbh,hbl,ND,0, wqkvh+(size_t)i*LQKV, wqkvl+(size_t)i*LQKV, ND,0, qkv,NQKV,
                      nullptr,nullptr,0,0, NT,NQKV,ND,1, bqkv+(size_t)i*NQKV,0,0, 0, nullptr,nullptr,0,0};
            launch_t(a); }
        flash_kernel<<<dim3(NS/128, NB*NH),256,FL_SMEM>>>(qkv, obh, obl);
        {   TArg a = {obh,obl,ND,0, woh+(size_t)i*LDD, wol+(size_t)i*LDD, ND,0, x,ND,
                      nullptr,nullptr,0,0, NT,ND,ND,1, bo+(size_t)i*ND,0,0, 1, nullptr,nullptr,0,0};
            launch_t(a); }

        // ---- MoE (top-2, batched over experts via grid.z) ----
        ln_kernel<<<NT,256>>>(x, ln2g+(size_t)i*ND, ln2b+(size_t)i*ND, h, hbh, hbl);
        zero_cnt_kernel<<<1,32>>>();
        router_kernel<<<NT/4, dim3(32,4)>>>(h, rw+(size_t)i*ND*NE, rb+(size_t)i*NE);
        {   TArg a = {hbh,hbl,ND,0,
                      w1h+(size_t)i*NE*NF*ND, w1l+(size_t)i*NE*NF*ND, ND,(long long)NF*ND,
                      nullptr,0,
                      h1h,h1l,NF,(long long)NT*NF,
                      NT,NF,ND,NE,
                      eb1+(size_t)i*NE*NF, NF, 1, 0,
                      eidx, ecnt, NT, 1};
            launch_t(a); }
        {   TArg a = {h1h,h1l,NF,(long long)NT*NF,
                      w2h+(size_t)i*NE*ND*NF, w2l+(size_t)i*NE*ND*NF, NF,(long long)ND*NF,
                      h2,ND,
                      nullptr,nullptr,0,(long long)NT*ND,
                      NT,ND,NF,NE,
                      eb2+(size_t)i*NE*ND, ND, 0, 0,
                      eidx, ecnt, NT, 0};
            launch_t(a); }
        moe_combine_kernel<<<NT,192>>>();
    }

    // ---- final LN + output projection ----
    ln_kernel<<<NT,256>>>(x, lnfg, lnfb, h, hbh, hbl);
    {   TArg a = {hbh,hbl,ND,0, wouth,woutl,ND,0, out,NV, nullptr,nullptr,0,0,
                  NT,NV,ND,1, outb,0,0, 0, nullptr,nullptr,0,0};
        launch_t(a); }
}